// round 12
// baseline (speedup 1.0000x reference)
#include <cuda_runtime.h>
#include <cstdint>

#define NRES 320
#define CDIM 128
#define NH 4
#define DH 32
#define NN (NRES*NRES)
#define AP 132   // padded row stride for MMA smem tiles

// ---------- tf32 mma helpers ----------
__device__ __forceinline__ uint32_t f2tf(float f) {
    uint32_t u; asm("cvt.rna.tf32.f32 %0, %1;" : "=r"(u) : "f"(f)); return u;
}
__device__ __forceinline__ void mma_tf32(float* d,
    uint32_t a0, uint32_t a1, uint32_t a2, uint32_t a3,
    uint32_t b0, uint32_t b1)
{
    asm volatile(
        "mma.sync.aligned.m16n8k8.row.col.f32.tf32.tf32.f32 "
        "{%0,%1,%2,%3}, {%4,%5,%6,%7}, {%8,%9}, {%0,%1,%2,%3};"
        : "+f"(d[0]), "+f"(d[1]), "+f"(d[2]), "+f"(d[3])
        : "r"(a0), "r"(a1), "r"(a2), "r"(a3), "r"(b0), "r"(b1));
}

// -------- device scratch --------
__device__ float g_q   [(size_t)NRES*NH*NRES*DH];   // [i][h][j][d]
__device__ float g_k   [(size_t)NRES*NH*NRES*DH];
__device__ float g_v   [(size_t)NRES*NH*NRES*DH];
__device__ float g_gate[(size_t)NRES*NH*NRES*DH];
__device__ float g_og  [(size_t)NN*CDIM];
__device__ float g_bias[(size_t)NH*NN];             // [h][q][j]
__device__ uint32_t g_wt[5*128*128];                // transposed tf32 weights [s][n][k]

// =====================================================================
// Kernel W: one-shot transpose+convert of the 5 weight matrices.
// =====================================================================
__global__ __launch_bounds__(256, 4) void kW(
    const float* __restrict__ wq, const float* __restrict__ wk,
    const float* __restrict__ wv, const float* __restrict__ wg,
    const float* __restrict__ wo)
{
    int idx = blockIdx.x * 256 + threadIdx.x;    // 5*16384 total
    int s = idx >> 14, r = idx & 16383;
    int n = r >> 7, k = r & 127;
    const float* W = (s == 0) ? wq : (s == 1) ? wk : (s == 2) ? wv
                   : (s == 3) ? wg : wo;
    g_wt[idx] = f2tf(W[k * 128 + n]);
}

// =====================================================================
// Kernel A (tensor, 1024 thr): LN + q/k/v/gate projections + tri bias.
// (unchanged from R11)
// =====================================================================
#define KA_AHI 0
#define KA_ALO (KA_AHI + 128*AP)
#define KA_WT  (KA_ALO + 128*AP)
#define KA_SG  (KA_WT  + 128*AP)
#define KA_SB  (KA_SG + 128)
#define KA_WB  (KA_SB + 128)
#define SMEM_A ((KA_WB + 512) * 4)

__global__ __launch_bounds__(1024, 1) void kA(
    const float* __restrict__ x,   const float* __restrict__ lng,
    const float* __restrict__ lnb, const float* __restrict__ wb,
    const float* __restrict__ bg)
{
    extern __shared__ float sm[];
    float* ahi_f = sm + KA_AHI;
    float* alo_f = sm + KA_ALO;
    float* sg    = sm + KA_SG;
    float* sb    = sm + KA_SB;
    float* wbs   = sm + KA_WB;
    uint32_t* ahi = (uint32_t*)ahi_f;
    uint32_t* alo = (uint32_t*)alo_f;
    uint32_t* wt  = (uint32_t*)(sm + KA_WT);

    int tid = threadIdx.x, lane = tid & 31, w = tid >> 5;
    int g2 = lane >> 2, cq = lane & 3;
    int rw = w & 7, nc = w >> 3;
    int colbase = nc * 32;
    int Rb = blockIdx.x * 128;

    if (tid < 128) { sg[tid] = lng[tid]; sb[tid] = lnb[tid]; }
    if (tid >= 128 && tid < 640) wbs[tid - 128] = wb[tid - 128];

    // ---- layernorm: 8 threads per row (16 elems each) ----
    int row = tid >> 3, sub = tid & 7;
    float xv[16];
    const float* xr = x + (size_t)(Rb + row) * CDIM + sub * 16;
    #pragma unroll
    for (int m4 = 0; m4 < 4; m4++) {
        float4 t = *(const float4*)(xr + m4 * 4);
        xv[m4*4+0] = t.x; xv[m4*4+1] = t.y; xv[m4*4+2] = t.z; xv[m4*4+3] = t.w;
    }
    float sum = 0.f, sq = 0.f;
    #pragma unroll
    for (int m = 0; m < 16; m++) { sum += xv[m]; sq += xv[m]*xv[m]; }
    #pragma unroll
    for (int off = 4; off >= 1; off >>= 1) {
        sum += __shfl_xor_sync(0xffffffffu, sum, off, 8);
        sq  += __shfl_xor_sync(0xffffffffu, sq,  off, 8);
    }
    float mu = sum * (1.f / CDIM);
    float rs = rsqrtf(sq * (1.f / CDIM) - mu * mu + 1e-5f);

    __syncthreads();   // sg/sb/wbs ready
    #pragma unroll
    for (int m = 0; m < 16; m++) {
        int c = sub * 16 + m;
        float val = (xv[m] - mu) * rs * sg[c] + sb[c];
        uint32_t hb = f2tf(val);
        ahi[row * AP + c] = hb;
        alo[row * AP + c] = f2tf(val - __uint_as_float(hb));
    }
    __syncthreads();   // A ready

    // ---- triangle bias: 512 items on first 512 threads ----
    if (tid < 512) {
        int r = tid >> 2, h2 = tid & 3;
        float acc = 0.f;
        #pragma unroll 8
        for (int kk = 0; kk < CDIM; kk++)
            acc += (ahi_f[r * AP + kk] + alo_f[r * AP + kk]) * wbs[kk * NH + h2];
        g_bias[(size_t)h2 * NN + Rb + r] = acc;
    }

    // ---- 4 projection chunks ----
    int r0 = (rw << 4) + g2;
    int R0 = Rb + r0, R1 = R0 + 8;
    int i0 = R0 / NRES, j0 = R0 - i0 * NRES;
    int i1 = R1 / NRES, j1 = R1 - i1 * NRES;

    #pragma unroll 1
    for (int s = 0; s < 4; s++) {
        const uint4* src = (const uint4*)(g_wt + s * 16384);
        #pragma unroll
        for (int i = 0; i < 4; i++) {
            int idx4 = tid + i * 1024;
            int n = idx4 >> 5, k4 = idx4 & 31;
            uint4 vv = __ldg(&src[idx4]);
            *(uint4*)&wt[n * AP + k4 * 4] = vv;
        }
        __syncthreads();

        float acc[4][4];
        #pragma unroll
        for (int t = 0; t < 4; t++)
            #pragma unroll
            for (int e = 0; e < 4; e++) acc[t][e] = 0.f;

        #pragma unroll 4
        for (int ks = 0; ks < 16; ks++) {
            int kc = ks * 8;
            uint32_t h0 = ahi[r0 * AP + kc + cq];
            uint32_t h1 = ahi[(r0 + 8) * AP + kc + cq];
            uint32_t h2_ = ahi[r0 * AP + kc + cq + 4];
            uint32_t h3 = ahi[(r0 + 8) * AP + kc + cq + 4];
            if (s != 3) {
                uint32_t l0 = alo[r0 * AP + kc + cq];
                uint32_t l1 = alo[(r0 + 8) * AP + kc + cq];
                uint32_t l2 = alo[r0 * AP + kc + cq + 4];
                uint32_t l3 = alo[(r0 + 8) * AP + kc + cq + 4];
                #pragma unroll
                for (int t = 0; t < 4; t++) {
                    int n0 = (colbase + t * 8 + g2) * AP + kc;
                    uint32_t b0 = wt[n0 + cq];
                    uint32_t b1 = wt[n0 + cq + 4];
                    mma_tf32(acc[t], h0, h1, h2_, h3, b0, b1);
                    mma_tf32(acc[t], l0, l1, l2, l3, b0, b1);
                }
            } else {
                #pragma unroll
                for (int t = 0; t < 4; t++) {
                    int n0 = (colbase + t * 8 + g2) * AP + kc;
                    uint32_t b0 = wt[n0 + cq];
                    uint32_t b1 = wt[n0 + cq + 4];
                    mma_tf32(acc[t], h0, h1, h2_, h3, b0, b1);
                }
            }
        }

        if (s == 0) {
            #pragma unroll
            for (int t = 0; t < 4; t++)
                #pragma unroll
                for (int e = 0; e < 4; e++) acc[t][e] *= 0.17677669529663687f;
        }
        if (s == 3) {
            #pragma unroll
            for (int t = 0; t < 4; t++) {
                int col = colbase + t * 8 + cq * 2;
                float2 bgv = __ldg((const float2*)&bg[col]);
                acc[t][0] = 1.f / (1.f + __expf(-(acc[t][0] + bgv.x)));
                acc[t][1] = 1.f / (1.f + __expf(-(acc[t][1] + bgv.y)));
                acc[t][2] = 1.f / (1.f + __expf(-(acc[t][2] + bgv.x)));
                acc[t][3] = 1.f / (1.f + __expf(-(acc[t][3] + bgv.y)));
            }
        }
        float* dst = (s == 0) ? g_q : (s == 1) ? g_k : (s == 2) ? g_v : g_gate;
        #pragma unroll
        for (int t = 0; t < 4; t++) {
            int col = colbase + t * 8 + cq * 2;
            int h = col >> 5, d = col & 31;
            *(float2*)&dst[(((size_t)i0 * NH + h) * NRES + j0) * DH + d] =
                make_float2(acc[t][0], acc[t][1]);
            *(float2*)&dst[(((size_t)i1 * NH + h) * NRES + j1) * DH + d] =
                make_float2(acc[t][2], acc[t][3]);
        }
        __syncthreads();
    }
}

// =====================================================================
// Kernel B: attention per (i,h), tf32 mma, 256 thr, 2 blocks/SM.
// P staged in 16-kj chunks (per-warp 16x20 buffer) -> smem 110KB.
// =====================================================================
#define KS_OFF    0
#define VS_OFF    (KS_OFF + 320*36)
#define PS_OFF    (VS_OFF + 320*36)            // 8 warps x [16][20]
#define MSK_OFF   (PS_OFF + 8*16*20)
#define RED_OFF   (MSK_OFF + 320)              // 8 warps x 16 rows x {m,s}
#define OPART_OFF (RED_OFF + 8*16*2)           // 4 pairs x [16][32]
#define SMEM_B    ((OPART_OFF + 4*16*32) * 4)

__global__ __launch_bounds__(256, 2) void kB(const float* __restrict__ mask)
{
    extern __shared__ float sm[];
    uint32_t* ksu = (uint32_t*)(sm + KS_OFF);
    uint32_t* vsu = (uint32_t*)(sm + VS_OFF);
    uint32_t* psu = (uint32_t*)(sm + PS_OFF);
    float* msk   = sm + MSK_OFF;
    float* red   = sm + RED_OFF;
    float* opart = sm + OPART_OFF;

    int i = blockIdx.x, h = blockIdx.y;
    int tid = threadIdx.x, lane = tid & 31, w = tid >> 5;
    int p2 = w >> 1, half = w & 1;
    int khalf = half * 160;
    int g = lane >> 2, c = lane & 3;

    size_t base = ((size_t)i * NH + h) * (NRES * DH);
    const float* kg = g_k    + base;
    const float* qg = g_q    + base;
    const float* vg = g_v    + base;
    const float* gg = g_gate + base;

    for (int idx = tid; idx < NRES * DH; idx += 256) {
        int kk = idx >> 5, d = idx & 31;
        ksu[kk * 36 + d] = f2tf(kg[idx]);
        vsu[kk * 36 + d] = f2tf(vg[idx]);
    }
    for (int idx = tid; idx < NRES; idx += 256)
        msk[idx] = 1.0e9f * (mask[(size_t)i * NRES + idx] - 1.f);

    const float* bias_h = g_bias + (size_t)h * NN;
    uint32_t* pw = psu + w * 16 * 20;

    __syncthreads();

    #pragma unroll 1
    for (int p = 0; p < 5; p++) {
        int qbase = p * 64 + p2 * 16;

        // ---- S = Q_tile x K_half^T : Q fragments direct from global ----
        float s[20][4];
        #pragma unroll
        for (int t = 0; t < 20; t++)
            #pragma unroll
            for (int e = 0; e < 4; e++) s[t][e] = 0.f;

        #pragma unroll
        for (int ds = 0; ds < 4; ds++) {
            int dc = ds * 8;
            const float* q0 = &qg[(qbase + g) * DH + dc];
            const float* q1 = &qg[(qbase + g + 8) * DH + dc];
            uint32_t a0 = f2tf(__ldg(q0 + c));
            uint32_t a1 = f2tf(__ldg(q1 + c));
            uint32_t a2 = f2tf(__ldg(q0 + c + 4));
            uint32_t a3 = f2tf(__ldg(q1 + c + 4));
            #pragma unroll
            for (int t = 0; t < 20; t++) {
                int n0 = (khalf + t * 8 + g) * 36 + dc;
                uint32_t b0 = ksu[n0 + c];
                uint32_t b1 = ksu[n0 + c + 4];
                mma_tf32(s[t], a0, a1, a2, a3, b0, b1);
            }
        }

        int row0 = qbase + g, row1 = row0 + 8;
        #pragma unroll
        for (int t = 0; t < 20; t++) {
            int col = khalf + t * 8 + c * 2;
            float2 mk = *(const float2*)&msk[col];
            float2 bA = __ldg((const float2*)&bias_h[(size_t)row0 * NRES + col]);
            float2 bB = __ldg((const float2*)&bias_h[(size_t)row1 * NRES + col]);
            s[t][0] += bA.x + mk.x;  s[t][1] += bA.y + mk.y;
            s[t][2] += bB.x + mk.x;  s[t][3] += bB.y + mk.y;
        }

        // ---- local softmax over 160 ----
        float mA = -1e30f, mB = -1e30f;
        #pragma unroll
        for (int t = 0; t < 20; t++) {
            mA = fmaxf(mA, fmaxf(s[t][0], s[t][1]));
            mB = fmaxf(mB, fmaxf(s[t][2], s[t][3]));
        }
        mA = fmaxf(mA, __shfl_xor_sync(0xffffffffu, mA, 1));
        mB = fmaxf(mB, __shfl_xor_sync(0xffffffffu, mB, 1));
        mA = fmaxf(mA, __shfl_xor_sync(0xffffffffu, mA, 2));
        mB = fmaxf(mB, __shfl_xor_sync(0xffffffffu, mB, 2));

        float sA = 0.f, sB = 0.f;
        #pragma unroll
        for (int t = 0; t < 20; t++) {
            s[t][0] = __expf(s[t][0] - mA); sA += s[t][0];
            s[t][1] = __expf(s[t][1] - mA); sA += s[t][1];
            s[t][2] = __expf(s[t][2] - mB); sB += s[t][2];
            s[t][3] = __expf(s[t][3] - mB); sB += s[t][3];
        }
        sA += __shfl_xor_sync(0xffffffffu, sA, 1);
        sB += __shfl_xor_sync(0xffffffffu, sB, 1);
        sA += __shfl_xor_sync(0xffffffffu, sA, 2);
        sB += __shfl_xor_sync(0xffffffffu, sB, 2);

        if (c == 0) {
            red[(w * 16 + g)     * 2]     = mA;
            red[(w * 16 + g)     * 2 + 1] = sA;
            red[(w * 16 + g + 8) * 2]     = mB;
            red[(w * 16 + g + 8) * 2 + 1] = sB;
        }
        __syncthreads();

        // ---- merge with partner half ----
        int wo = w ^ 1;
        float moA = red[(wo * 16 + g) * 2],     soA = red[(wo * 16 + g) * 2 + 1];
        float moB = red[(wo * 16 + g + 8) * 2], soB = red[(wo * 16 + g + 8) * 2 + 1];
        float MA = fmaxf(mA, moA), MB = fmaxf(mB, moB);
        float eA = __expf(mA - MA), eB = __expf(mB - MB);
        float facA = eA / (sA * eA + soA * __expf(moA - MA));
        float facB = eB / (sB * eB + soB * __expf(moB - MB));

        // ---- O = P x V_half : P staged in 16-kj chunks ----
        float o[4][4];
        #pragma unroll
        for (int t = 0; t < 4; t++)
            #pragma unroll
            for (int e = 0; e < 4; e++) o[t][e] = 0.f;

        #pragma unroll 2
        for (int tc = 0; tc < 10; tc++) {
            // stage this chunk's P (t = 2*tc, 2*tc+1)
            #pragma unroll
            for (int tt = 0; tt < 2; tt++) {
                int t = tc * 2 + tt;
                int kl = tt * 8 + c * 2;
                *(uint2*)&pw[g * 20 + kl] =
                    make_uint2(f2tf(s[t][0] * facA), f2tf(s[t][1] * facA));
                *(uint2*)&pw[(g + 8) * 20 + kl] =
                    make_uint2(f2tf(s[t][2] * facB), f2tf(s[t][3] * facB));
            }
            __syncwarp();
            #pragma unroll
            for (int ks = 0; ks < 2; ks++) {
                int kc = ks * 8;
                uint32_t a0 = pw[g * 20 + kc + c];
                uint32_t a1 = pw[(g + 8) * 20 + kc + c];
                uint32_t a2 = pw[g * 20 + kc + c + 4];
                uint32_t a3 = pw[(g + 8) * 20 + kc + c + 4];
                int kglob = khalf + (tc * 2 + ks) * 8;
                int vr0 = (kglob + c) * 36;
                int vr1 = (kglob + c + 4) * 36;
                #pragma unroll
                for (int t = 0; t < 4; t++) {
                    uint32_t b0 = vsu[vr0 + t * 8 + g];
                    uint32_t b1 = vsu[vr1 + t * 8 + g];
                    mma_tf32(o[t], a0, a1, a2, a3, b0, b1);
                }
            }
            __syncwarp();   // protect chunk buffer reuse
        }

        // ---- pair merge + gate + store ----
        if (half) {
            #pragma unroll
            for (int t = 0; t < 4; t++) {
                int col = t * 8 + c * 2;
                *(float2*)&opart[(p2 * 16 + g) * 32 + col]     = make_float2(o[t][0], o[t][1]);
                *(float2*)&opart[(p2 * 16 + g + 8) * 32 + col] = make_float2(o[t][2], o[t][3]);
            }
        }
        __syncthreads();
        if (!half) {
            #pragma unroll
            for (int t = 0; t < 4; t++) {
                int col = t * 8 + c * 2;
                float2 qa = *(const float2*)&opart[(p2 * 16 + g) * 32 + col];
                float2 qb = *(const float2*)&opart[(p2 * 16 + g + 8) * 32 + col];
                float2 gA = __ldg((const float2*)&gg[row0 * 32 + col]);
                float2 gB = __ldg((const float2*)&gg[row1 * 32 + col]);
                float2 rA = make_float2((o[t][0] + qa.x) * gA.x, (o[t][1] + qa.y) * gA.y);
                float2 rB = make_float2((o[t][2] + qb.x) * gB.x, (o[t][3] + qb.y) * gB.y);
                *(float2*)&g_og[((size_t)i * NRES + row0) * CDIM + h * DH + col] = rA;
                *(float2*)&g_og[((size_t)i * NRES + row1) * CDIM + h * DH + col] = rB;
            }
        }
        __syncthreads();
    }
}

// =====================================================================
// Kernel C (tensor, 1024 thr): out = og @ wo + bo. (unchanged)
// =====================================================================
#define KC_A  0
#define KC_WT (KC_A + 128*AP)
#define SMEM_C ((KC_WT + 128*AP) * 4)

__global__ __launch_bounds__(1024, 1) void kC(
    const float* __restrict__ bo, float* __restrict__ out)
{
    extern __shared__ float sm[];
    uint32_t* ao = (uint32_t*)(sm + KC_A);
    uint32_t* wt = (uint32_t*)(sm + KC_WT);

    int tid = threadIdx.x, lane = tid & 31, w = tid >> 5;
    int g2 = lane >> 2, cq = lane & 3;
    int rw = w & 7, nc = w >> 3;
    int colbase = nc * 32;
    int Rb = blockIdx.x * 128;

    const uint4* wsrc = (const uint4*)(g_wt + 4 * 16384);
    const float4* asrc = (const float4*)(g_og + (size_t)Rb * CDIM);
    #pragma unroll
    for (int i = 0; i < 4; i++) {
        int idx4 = tid + i * 1024;
        int n = idx4 >> 5, k4 = idx4 & 31;
        uint4 wv = __ldg(&wsrc[idx4]);
        *(uint4*)&wt[n * AP + k4 * 4] = wv;
        float4 av = asrc[idx4];
        uint4 at;
        at.x = f2tf(av.x); at.y = f2tf(av.y); at.z = f2tf(av.z); at.w = f2tf(av.w);
        *(uint4*)&ao[n * AP + k4 * 4] = at;
    }
    __syncthreads();

    int r0 = (rw << 4) + g2;

    float acc[4][4];
    #pragma unroll
    for (int t = 0; t < 4; t++)
        #pragma unroll
        for (int e = 0; e < 4; e++) acc[t][e] = 0.f;

    #pragma unroll 4
    for (int ks = 0; ks < 16; ks++) {
        int kc = ks * 8;
        uint32_t a0 = ao[r0 * AP + kc + cq];
        uint32_t a1 = ao[(r0 + 8) * AP + kc + cq];
        uint32_t a2 = ao[r0 * AP + kc + cq + 4];
        uint32_t a3 = ao[(r0 + 8) * AP + kc + cq + 4];
        #pragma unroll
        for (int t = 0; t < 4; t++) {
            int n0 = (colbase + t * 8 + g2) * AP + kc;
            uint32_t b0 = wt[n0 + cq];
            uint32_t b1 = wt[n0 + cq + 4];
            mma_tf32(acc[t], a0, a1, a2, a3, b0, b1);
        }
    }

    #pragma unroll
    for (int t = 0; t < 4; t++) {
        int col = colbase + t * 8 + cq * 2;
        float2 bb = __ldg((const float2*)&bo[col]);
        *(float2*)&out[(size_t)(Rb + r0) * CDIM + col] =
            make_float2(acc[t][0] + bb.x, acc[t][1] + bb.y);
        *(float2*)&out[(size_t)(Rb + r0 + 8) * CDIM + col] =
            make_float2(acc[t][2] + bb.x, acc[t][3] + bb.y);
    }
}

// =====================================================================
extern "C" void kernel_launch(void* const* d_in, const int* in_sizes, int n_in,
                              void* d_out, int out_size)
{
    const float* x    = (const float*)d_in[0];
    const float* mask = (const float*)d_in[1];
    const float* lng  = (const float*)d_in[2];
    const float* lnb  = (const float*)d_in[3];
    const float* wb   = (const float*)d_in[4];
    const float* wq   = (const float*)d_in[5];
    const float* wk   = (const float*)d_in[6];
    const float* wv   = (const float*)d_in[7];
    const float* wg   = (const float*)d_in[8];
    const float* bg   = (const float*)d_in[9];
    const float* wo   = (const float*)d_in[10];
    const float* bo   = (const float*)d_in[11];
    float* out = (float*)d_out;

    cudaFuncSetAttribute(kA, cudaFuncAttributeMaxDynamicSharedMemorySize, SMEM_A);
    cudaFuncSetAttribute(kB, cudaFuncAttributeMaxDynamicSharedMemorySize, SMEM_B);
    cudaFuncSetAttribute(kC, cudaFuncAttributeMaxDynamicSharedMemorySize, SMEM_C);

    kW<<<320, 256>>>(wq, wk, wv, wg, wo);
    kA<<<NN / 128, 1024, SMEM_A>>>(x, lng, lnb, wb, bg);
    kB<<<dim3(NRES, NH), 256, SMEM_B>>>(mask);
    kC<<<NN / 128, 1024, SMEM_C>>>(bo, out);
}

// round 13
// speedup vs baseline: 1.8336x; 1.8336x over previous
#include <cuda_runtime.h>
#include <cstdint>

#define NRES 320
#define CDIM 128
#define NH 4
#define DH 32
#define NN (NRES*NRES)
#define AP 132   // padded row stride for MMA smem tiles

// ---------- tf32 mma helpers ----------
__device__ __forceinline__ uint32_t f2tf(float f) {
    uint32_t u; asm("cvt.rna.tf32.f32 %0, %1;" : "=r"(u) : "f"(f)); return u;
}
__device__ __forceinline__ void mma_tf32(float* d,
    uint32_t a0, uint32_t a1, uint32_t a2, uint32_t a3,
    uint32_t b0, uint32_t b1)
{
    asm volatile(
        "mma.sync.aligned.m16n8k8.row.col.f32.tf32.tf32.f32 "
        "{%0,%1,%2,%3}, {%4,%5,%6,%7}, {%8,%9}, {%0,%1,%2,%3};"
        : "+f"(d[0]), "+f"(d[1]), "+f"(d[2]), "+f"(d[3])
        : "r"(a0), "r"(a1), "r"(a2), "r"(a3), "r"(b0), "r"(b1));
}
#define PAIR_BAR(id) asm volatile("bar.sync %0, 64;" :: "r"(id) : "memory")

// -------- device scratch --------
__device__ float g_q   [(size_t)NRES*NH*NRES*DH];   // [i][h][j][d]
__device__ float g_k   [(size_t)NRES*NH*NRES*DH];
__device__ float g_v   [(size_t)NRES*NH*NRES*DH];
__device__ float g_gate[(size_t)NRES*NH*NRES*DH];
__device__ float g_og  [(size_t)NN*CDIM];
__device__ float g_bias[(size_t)NH*NN];             // [h][q][j]
__device__ uint32_t g_wt[5*128*128];                // transposed tf32 weights [s][n][k]

// =====================================================================
// Kernel W: one-shot transpose+convert of the 5 weight matrices.
// =====================================================================
__global__ __launch_bounds__(256, 4) void kW(
    const float* __restrict__ wq, const float* __restrict__ wk,
    const float* __restrict__ wv, const float* __restrict__ wg,
    const float* __restrict__ wo)
{
    int idx = blockIdx.x * 256 + threadIdx.x;    // 5*16384 total
    int s = idx >> 14, r = idx & 16383;
    int n = r >> 7, k = r & 127;
    const float* W = (s == 0) ? wq : (s == 1) ? wk : (s == 2) ? wv
                   : (s == 3) ? wg : wo;
    g_wt[idx] = f2tf(W[k * 128 + n]);
}

// =====================================================================
// Kernel A (tensor, 1024 thr): LN + q/k/v/gate projections + tri bias.
// (unchanged from R11)
// =====================================================================
#define KA_AHI 0
#define KA_ALO (KA_AHI + 128*AP)
#define KA_WT  (KA_ALO + 128*AP)
#define KA_SG  (KA_WT  + 128*AP)
#define KA_SB  (KA_SG + 128)
#define KA_WB  (KA_SB + 128)
#define SMEM_A ((KA_WB + 512) * 4)

__global__ __launch_bounds__(1024, 1) void kA(
    const float* __restrict__ x,   const float* __restrict__ lng,
    const float* __restrict__ lnb, const float* __restrict__ wb,
    const float* __restrict__ bg)
{
    extern __shared__ float sm[];
    float* ahi_f = sm + KA_AHI;
    float* alo_f = sm + KA_ALO;
    float* sg    = sm + KA_SG;
    float* sb    = sm + KA_SB;
    float* wbs   = sm + KA_WB;
    uint32_t* ahi = (uint32_t*)ahi_f;
    uint32_t* alo = (uint32_t*)alo_f;
    uint32_t* wt  = (uint32_t*)(sm + KA_WT);

    int tid = threadIdx.x, lane = tid & 31, w = tid >> 5;
    int g2 = lane >> 2, cq = lane & 3;
    int rw = w & 7, nc = w >> 3;
    int colbase = nc * 32;
    int Rb = blockIdx.x * 128;

    if (tid < 128) { sg[tid] = lng[tid]; sb[tid] = lnb[tid]; }
    if (tid >= 128 && tid < 640) wbs[tid - 128] = wb[tid - 128];

    // ---- layernorm: 8 threads per row (16 elems each) ----
    int row = tid >> 3, sub = tid & 7;
    float xv[16];
    const float* xr = x + (size_t)(Rb + row) * CDIM + sub * 16;
    #pragma unroll
    for (int m4 = 0; m4 < 4; m4++) {
        float4 t = *(const float4*)(xr + m4 * 4);
        xv[m4*4+0] = t.x; xv[m4*4+1] = t.y; xv[m4*4+2] = t.z; xv[m4*4+3] = t.w;
    }
    float sum = 0.f, sq = 0.f;
    #pragma unroll
    for (int m = 0; m < 16; m++) { sum += xv[m]; sq += xv[m]*xv[m]; }
    #pragma unroll
    for (int off = 4; off >= 1; off >>= 1) {
        sum += __shfl_xor_sync(0xffffffffu, sum, off, 8);
        sq  += __shfl_xor_sync(0xffffffffu, sq,  off, 8);
    }
    float mu = sum * (1.f / CDIM);
    float rs = rsqrtf(sq * (1.f / CDIM) - mu * mu + 1e-5f);

    __syncthreads();   // sg/sb/wbs ready
    #pragma unroll
    for (int m = 0; m < 16; m++) {
        int c = sub * 16 + m;
        float val = (xv[m] - mu) * rs * sg[c] + sb[c];
        uint32_t hb = f2tf(val);
        ahi[row * AP + c] = hb;
        alo[row * AP + c] = f2tf(val - __uint_as_float(hb));
    }
    __syncthreads();   // A ready

    // ---- triangle bias: 512 items on first 512 threads ----
    if (tid < 512) {
        int r = tid >> 2, h2 = tid & 3;
        float acc = 0.f;
        #pragma unroll 8
        for (int kk = 0; kk < CDIM; kk++)
            acc += (ahi_f[r * AP + kk] + alo_f[r * AP + kk]) * wbs[kk * NH + h2];
        g_bias[(size_t)h2 * NN + Rb + r] = acc;
    }

    // ---- 4 projection chunks ----
    int r0 = (rw << 4) + g2;
    int R0 = Rb + r0, R1 = R0 + 8;
    int i0 = R0 / NRES, j0 = R0 - i0 * NRES;
    int i1 = R1 / NRES, j1 = R1 - i1 * NRES;

    #pragma unroll 1
    for (int s = 0; s < 4; s++) {
        const uint4* src = (const uint4*)(g_wt + s * 16384);
        #pragma unroll
        for (int i = 0; i < 4; i++) {
            int idx4 = tid + i * 1024;
            int n = idx4 >> 5, k4 = idx4 & 31;
            uint4 vv = __ldg(&src[idx4]);
            *(uint4*)&wt[n * AP + k4 * 4] = vv;
        }
        __syncthreads();

        float acc[4][4];
        #pragma unroll
        for (int t = 0; t < 4; t++)
            #pragma unroll
            for (int e = 0; e < 4; e++) acc[t][e] = 0.f;

        #pragma unroll 4
        for (int ks = 0; ks < 16; ks++) {
            int kc = ks * 8;
            uint32_t h0 = ahi[r0 * AP + kc + cq];
            uint32_t h1 = ahi[(r0 + 8) * AP + kc + cq];
            uint32_t h2_ = ahi[r0 * AP + kc + cq + 4];
            uint32_t h3 = ahi[(r0 + 8) * AP + kc + cq + 4];
            if (s != 3) {
                uint32_t l0 = alo[r0 * AP + kc + cq];
                uint32_t l1 = alo[(r0 + 8) * AP + kc + cq];
                uint32_t l2 = alo[r0 * AP + kc + cq + 4];
                uint32_t l3 = alo[(r0 + 8) * AP + kc + cq + 4];
                #pragma unroll
                for (int t = 0; t < 4; t++) {
                    int n0 = (colbase + t * 8 + g2) * AP + kc;
                    uint32_t b0 = wt[n0 + cq];
                    uint32_t b1 = wt[n0 + cq + 4];
                    mma_tf32(acc[t], h0, h1, h2_, h3, b0, b1);
                    mma_tf32(acc[t], l0, l1, l2, l3, b0, b1);
                }
            } else {
                #pragma unroll
                for (int t = 0; t < 4; t++) {
                    int n0 = (colbase + t * 8 + g2) * AP + kc;
                    uint32_t b0 = wt[n0 + cq];
                    uint32_t b1 = wt[n0 + cq + 4];
                    mma_tf32(acc[t], h0, h1, h2_, h3, b0, b1);
                }
            }
        }

        if (s == 0) {
            #pragma unroll
            for (int t = 0; t < 4; t++)
                #pragma unroll
                for (int e = 0; e < 4; e++) acc[t][e] *= 0.17677669529663687f;
        }
        if (s == 3) {
            #pragma unroll
            for (int t = 0; t < 4; t++) {
                int col = colbase + t * 8 + cq * 2;
                float2 bgv = __ldg((const float2*)&bg[col]);
                acc[t][0] = 1.f / (1.f + __expf(-(acc[t][0] + bgv.x)));
                acc[t][1] = 1.f / (1.f + __expf(-(acc[t][1] + bgv.y)));
                acc[t][2] = 1.f / (1.f + __expf(-(acc[t][2] + bgv.x)));
                acc[t][3] = 1.f / (1.f + __expf(-(acc[t][3] + bgv.y)));
            }
        }
        float* dst = (s == 0) ? g_q : (s == 1) ? g_k : (s == 2) ? g_v : g_gate;
        #pragma unroll
        for (int t = 0; t < 4; t++) {
            int col = colbase + t * 8 + cq * 2;
            int h = col >> 5, d = col & 31;
            *(float2*)&dst[(((size_t)i0 * NH + h) * NRES + j0) * DH + d] =
                make_float2(acc[t][0], acc[t][1]);
            *(float2*)&dst[(((size_t)i1 * NH + h) * NRES + j1) * DH + d] =
                make_float2(acc[t][2], acc[t][3]);
        }
        __syncthreads();
    }
}

// =====================================================================
// Kernel B: attention per (i,h), tf32 mma, 256 thr, occ 1 (R11 body)
// with PAIR-LOCAL named barriers instead of block-wide __syncthreads
// in the pass loop (4 pairs run desynchronized).
// =====================================================================
#define KS_OFF    0
#define VS_OFF    (KS_OFF + 320*36)
#define PS_OFF    (VS_OFF + 320*36)            // 8 warps x [16][164]
#define MSK_OFF   (PS_OFF + 8*16*164)
#define RED_OFF   (MSK_OFF + 320)              // 8 warps x 16 rows x {m,s}
#define OPART_OFF (RED_OFF + 8*16*2)           // 4 pairs x [16][32]
#define SMEM_B    ((OPART_OFF + 4*16*32) * 4)

__global__ __launch_bounds__(256, 1) void kB(const float* __restrict__ mask)
{
    extern __shared__ float sm[];
    uint32_t* ksu = (uint32_t*)(sm + KS_OFF);
    uint32_t* vsu = (uint32_t*)(sm + VS_OFF);
    uint32_t* psu = (uint32_t*)(sm + PS_OFF);
    float* msk   = sm + MSK_OFF;
    float* red   = sm + RED_OFF;
    float* opart = sm + OPART_OFF;

    int i = blockIdx.x, h = blockIdx.y;
    int tid = threadIdx.x, lane = tid & 31, w = tid >> 5;
    int p2 = w >> 1, half = w & 1;
    int bar_id = 1 + p2;
    int khalf = half * 160;
    int g = lane >> 2, c = lane & 3;

    size_t base = ((size_t)i * NH + h) * (NRES * DH);
    const float* kg = g_k    + base;
    const float* qg = g_q    + base;
    const float* vg = g_v    + base;
    const float* gg = g_gate + base;

    for (int idx = tid; idx < NRES * DH; idx += 256) {
        int kk = idx >> 5, d = idx & 31;
        ksu[kk * 36 + d] = f2tf(kg[idx]);
        vsu[kk * 36 + d] = f2tf(vg[idx]);
    }
    for (int idx = tid; idx < NRES; idx += 256)
        msk[idx] = 1.0e9f * (mask[(size_t)i * NRES + idx] - 1.f);

    const float* bias_h = g_bias + (size_t)h * NN;
    uint32_t* pw = psu + w * 16 * 164;

    __syncthreads();

    #pragma unroll 1
    for (int p = 0; p < 5; p++) {
        int qbase = p * 64 + p2 * 16;

        // ---- S = Q_tile x K_half^T : Q fragments direct from global ----
        float s[20][4];
        #pragma unroll
        for (int t = 0; t < 20; t++)
            #pragma unroll
            for (int e = 0; e < 4; e++) s[t][e] = 0.f;

        #pragma unroll
        for (int ds = 0; ds < 4; ds++) {
            int dc = ds * 8;
            const float* q0 = &qg[(qbase + g) * DH + dc];
            const float* q1 = &qg[(qbase + g + 8) * DH + dc];
            uint32_t a0 = f2tf(__ldg(q0 + c));
            uint32_t a1 = f2tf(__ldg(q1 + c));
            uint32_t a2 = f2tf(__ldg(q0 + c + 4));
            uint32_t a3 = f2tf(__ldg(q1 + c + 4));
            #pragma unroll
            for (int t = 0; t < 20; t++) {
                int n0 = (khalf + t * 8 + g) * 36 + dc;
                uint32_t b0 = ksu[n0 + c];
                uint32_t b1 = ksu[n0 + c + 4];
                mma_tf32(s[t], a0, a1, a2, a3, b0, b1);
            }
        }

        int row0 = qbase + g, row1 = row0 + 8;
        #pragma unroll
        for (int t = 0; t < 20; t++) {
            int col = khalf + t * 8 + c * 2;
            float2 mk = *(const float2*)&msk[col];
            float2 bA = __ldg((const float2*)&bias_h[(size_t)row0 * NRES + col]);
            float2 bB = __ldg((const float2*)&bias_h[(size_t)row1 * NRES + col]);
            s[t][0] += bA.x + mk.x;  s[t][1] += bA.y + mk.y;
            s[t][2] += bB.x + mk.x;  s[t][3] += bB.y + mk.y;
        }

        // ---- local softmax over 160 ----
        float mA = -1e30f, mB = -1e30f;
        #pragma unroll
        for (int t = 0; t < 20; t++) {
            mA = fmaxf(mA, fmaxf(s[t][0], s[t][1]));
            mB = fmaxf(mB, fmaxf(s[t][2], s[t][3]));
        }
        mA = fmaxf(mA, __shfl_xor_sync(0xffffffffu, mA, 1));
        mB = fmaxf(mB, __shfl_xor_sync(0xffffffffu, mB, 1));
        mA = fmaxf(mA, __shfl_xor_sync(0xffffffffu, mA, 2));
        mB = fmaxf(mB, __shfl_xor_sync(0xffffffffu, mB, 2));

        float sA = 0.f, sB = 0.f;
        #pragma unroll
        for (int t = 0; t < 20; t++) {
            s[t][0] = __expf(s[t][0] - mA); sA += s[t][0];
            s[t][1] = __expf(s[t][1] - mA); sA += s[t][1];
            s[t][2] = __expf(s[t][2] - mB); sB += s[t][2];
            s[t][3] = __expf(s[t][3] - mB); sB += s[t][3];
        }
        sA += __shfl_xor_sync(0xffffffffu, sA, 1);
        sB += __shfl_xor_sync(0xffffffffu, sB, 1);
        sA += __shfl_xor_sync(0xffffffffu, sA, 2);
        sB += __shfl_xor_sync(0xffffffffu, sB, 2);

        if (c == 0) {
            red[(w * 16 + g)     * 2]     = mA;
            red[(w * 16 + g)     * 2 + 1] = sA;
            red[(w * 16 + g + 8) * 2]     = mB;
            red[(w * 16 + g + 8) * 2 + 1] = sB;
        }
        PAIR_BAR(bar_id);

        // ---- merge with partner half ----
        int wo = w ^ 1;
        float moA = red[(wo * 16 + g) * 2],     soA = red[(wo * 16 + g) * 2 + 1];
        float moB = red[(wo * 16 + g + 8) * 2], soB = red[(wo * 16 + g + 8) * 2 + 1];
        float MA = fmaxf(mA, moA), MB = fmaxf(mB, moB);
        float eA = __expf(mA - MA), eB = __expf(mB - MB);
        float facA = eA / (sA * eA + soA * __expf(moA - MA));
        float facB = eB / (sB * eB + soB * __expf(moB - MB));

        // ---- P (scaled, tf32) to per-warp smem ----
        #pragma unroll
        for (int t = 0; t < 20; t++) {
            int kl = t * 8 + c * 2;
            uint32_t p0 = f2tf(s[t][0] * facA);
            uint32_t p1 = f2tf(s[t][1] * facA);
            uint32_t p2_ = f2tf(s[t][2] * facB);
            uint32_t p3 = f2tf(s[t][3] * facB);
            *(uint2*)&pw[g * 164 + kl]       = make_uint2(p0, p1);
            *(uint2*)&pw[(g + 8) * 164 + kl] = make_uint2(p2_, p3);
        }
        __syncwarp();

        // ---- O = P x V_half ----
        float o[4][4];
        #pragma unroll
        for (int t = 0; t < 4; t++)
            #pragma unroll
            for (int e = 0; e < 4; e++) o[t][e] = 0.f;

        #pragma unroll 4
        for (int ks = 0; ks < 20; ks++) {
            int kc = ks * 8;
            uint32_t a0 = pw[g * 164 + kc + c];
            uint32_t a1 = pw[(g + 8) * 164 + kc + c];
            uint32_t a2 = pw[g * 164 + kc + c + 4];
            uint32_t a3 = pw[(g + 8) * 164 + kc + c + 4];
            int vr0 = (khalf + kc + c) * 36;
            int vr1 = (khalf + kc + c + 4) * 36;
            #pragma unroll
            for (int t = 0; t < 4; t++) {
                uint32_t b0 = vsu[vr0 + t * 8 + g];
                uint32_t b1 = vsu[vr1 + t * 8 + g];
                mma_tf32(o[t], a0, a1, a2, a3, b0, b1);
            }
        }

        // ---- pair merge + gate + store ----
        if (half) {
            #pragma unroll
            for (int t = 0; t < 4; t++) {
                int col = t * 8 + c * 2;
                *(float2*)&opart[(p2 * 16 + g) * 32 + col]     = make_float2(o[t][0], o[t][1]);
                *(float2*)&opart[(p2 * 16 + g + 8) * 32 + col] = make_float2(o[t][2], o[t][3]);
            }
        }
        PAIR_BAR(bar_id);
        if (!half) {
            #pragma unroll
            for (int t = 0; t < 4; t++) {
                int col = t * 8 + c * 2;
                float2 qa = *(const float2*)&opart[(p2 * 16 + g) * 32 + col];
                float2 qb = *(const float2*)&opart[(p2 * 16 + g + 8) * 32 + col];
                float2 gA = __ldg((const float2*)&gg[row0 * 32 + col]);
                float2 gB = __ldg((const float2*)&gg[row1 * 32 + col]);
                float2 rA = make_float2((o[t][0] + qa.x) * gA.x, (o[t][1] + qa.y) * gA.y);
                float2 rB = make_float2((o[t][2] + qb.x) * gB.x, (o[t][3] + qb.y) * gB.y);
                *(float2*)&g_og[((size_t)i * NRES + row0) * CDIM + h * DH + col] = rA;
                *(float2*)&g_og[((size_t)i * NRES + row1) * CDIM + h * DH + col] = rB;
            }
        }
        PAIR_BAR(bar_id);
    }
}

// =====================================================================
// Kernel C (tensor, 1024 thr): out = og @ wo + bo. (unchanged)
// =====================================================================
#define KC_A  0
#define KC_WT (KC_A + 128*AP)
#define SMEM_C ((KC_WT + 128*AP) * 4)

__global__ __launch_bounds__(1024, 1) void kC(
    const float* __restrict__ bo, float* __restrict__ out)
{
    extern __shared__ float sm[];
    uint32_t* ao = (uint32_t*)(sm + KC_A);
    uint32_t* wt = (uint32_t*)(sm + KC_WT);

    int tid = threadIdx.x, lane = tid & 31, w = tid >> 5;
    int g2 = lane >> 2, cq = lane & 3;
    int rw = w & 7, nc = w >> 3;
    int colbase = nc * 32;
    int Rb = blockIdx.x * 128;

    const uint4* wsrc = (const uint4*)(g_wt + 4 * 16384);
    const float4* asrc = (const float4*)(g_og + (size_t)Rb * CDIM);
    #pragma unroll
    for (int i = 0; i < 4; i++) {
        int idx4 = tid + i * 1024;
        int n = idx4 >> 5, k4 = idx4 & 31;
        uint4 wv = __ldg(&wsrc[idx4]);
        *(uint4*)&wt[n * AP + k4 * 4] = wv;
        float4 av = asrc[idx4];
        uint4 at;
        at.x = f2tf(av.x); at.y = f2tf(av.y); at.z = f2tf(av.z); at.w = f2tf(av.w);
        *(uint4*)&ao[n * AP + k4 * 4] = at;
    }
    __syncthreads();

    int r0 = (rw << 4) + g2;

    float acc[4][4];
    #pragma unroll
    for (int t = 0; t < 4; t++)
        #pragma unroll
        for (int e = 0; e < 4; e++) acc[t][e] = 0.f;

    #pragma unroll 4
    for (int ks = 0; ks < 16; ks++) {
        int kc = ks * 8;
        uint32_t a0 = ao[r0 * AP + kc + cq];
        uint32_t a1 = ao[(r0 + 8) * AP + kc + cq];
        uint32_t a2 = ao[r0 * AP + kc + cq + 4];
        uint32_t a3 = ao[(r0 + 8) * AP + kc + cq + 4];
        #pragma unroll
        for (int t = 0; t < 4; t++) {
            int n0 = (colbase + t * 8 + g2) * AP + kc;
            uint32_t b0 = wt[n0 + cq];
            uint32_t b1 = wt[n0 + cq + 4];
            mma_tf32(acc[t], a0, a1, a2, a3, b0, b1);
        }
    }

    #pragma unroll
    for (int t = 0; t < 4; t++) {
        int col = colbase + t * 8 + cq * 2;
        float2 bb = __ldg((const float2*)&bo[col]);
        *(float2*)&out[(size_t)(Rb + r0) * CDIM + col] =
            make_float2(acc[t][0] + bb.x, acc[t][1] + bb.y);
        *(float2*)&out[(size_t)(Rb + r0 + 8) * CDIM + col] =
            make_float2(acc[t][2] + bb.x, acc[t][3] + bb.y);
    }
}

// =====================================================================
extern "C" void kernel_launch(void* const* d_in, const int* in_sizes, int n_in,
                              void* d_out, int out_size)
{
    const float* x    = (const float*)d_in[0];
    const float* mask = (const float*)d_in[1];
    const float* lng  = (const float*)d_in[2];
    const float* lnb  = (const float*)d_in[3];
    const float* wb   = (const float*)d_in[4];
    const float* wq   = (const float*)d_in[5];
    const float* wk   = (const float*)d_in[6];
    const float* wv   = (const float*)d_in[7];
    const float* wg   = (const float*)d_in[8];
    const float* bg   = (const float*)d_in[9];
    const float* wo   = (const float*)d_in[10];
    const float* bo   = (const float*)d_in[11];
    float* out = (float*)d_out;

    cudaFuncSetAttribute(kA, cudaFuncAttributeMaxDynamicSharedMemorySize, SMEM_A);
    cudaFuncSetAttribute(kB, cudaFuncAttributeMaxDynamicSharedMemorySize, SMEM_B);
    cudaFuncSetAttribute(kC, cudaFuncAttributeMaxDynamicSharedMemorySize, SMEM_C);

    kW<<<320, 256>>>(wq, wk, wv, wg, wo);
    kA<<<NN / 128, 1024, SMEM_A>>>(x, lng, lnb, wb, bg);
    kB<<<dim3(NRES, NH), 256, SMEM_B>>>(mask);
    kC<<<NN / 128, 1024, SMEM_C>>>(bo, out);
}

// round 14
// speedup vs baseline: 1.9394x; 1.0577x over previous
#include <cuda_runtime.h>
#include <cstdint>

#define NRES 320
#define CDIM 128
#define NH 4
#define DH 32
#define NN (NRES*NRES)
#define AP 132   // padded row stride for MMA smem tiles

// ---------- tf32 mma helpers ----------
__device__ __forceinline__ uint32_t f2tf(float f) {
    uint32_t u; asm("cvt.rna.tf32.f32 %0, %1;" : "=r"(u) : "f"(f)); return u;
}
__device__ __forceinline__ void mma_tf32(float* d,
    uint32_t a0, uint32_t a1, uint32_t a2, uint32_t a3,
    uint32_t b0, uint32_t b1)
{
    asm volatile(
        "mma.sync.aligned.m16n8k8.row.col.f32.tf32.tf32.f32 "
        "{%0,%1,%2,%3}, {%4,%5,%6,%7}, {%8,%9}, {%0,%1,%2,%3};"
        : "+f"(d[0]), "+f"(d[1]), "+f"(d[2]), "+f"(d[3])
        : "r"(a0), "r"(a1), "r"(a2), "r"(a3), "r"(b0), "r"(b1));
}

// -------- device scratch --------
__device__ float g_q   [(size_t)NRES*NH*NRES*DH];   // [i][h][j][d]
__device__ float g_k   [(size_t)NRES*NH*NRES*DH];
__device__ float g_v   [(size_t)NRES*NH*NRES*DH];
__device__ float g_gate[(size_t)NRES*NH*NRES*DH];
__device__ float g_og  [(size_t)NN*CDIM];
__device__ float g_bias[(size_t)NH*NN];             // [h][q][j]
__device__ uint32_t g_wt[5*128*128];                // transposed tf32 weights [s][n][k]

// =====================================================================
// Kernel W: one-shot transpose+convert of the 5 weight matrices.
// =====================================================================
__global__ __launch_bounds__(256, 4) void kW(
    const float* __restrict__ wq, const float* __restrict__ wk,
    const float* __restrict__ wv, const float* __restrict__ wg,
    const float* __restrict__ wo)
{
    int idx = blockIdx.x * 256 + threadIdx.x;    // 5*16384 total
    int s = idx >> 14, r = idx & 16383;
    int n = r >> 7, k = r & 127;
    const float* W = (s == 0) ? wq : (s == 1) ? wk : (s == 2) ? wv
                   : (s == 3) ? wg : wo;
    g_wt[idx] = f2tf(W[k * 128 + n]);
}

// =====================================================================
// Kernel A (tensor, 1024 thr): LN + q/k/v/gate projections + tri bias.
// (unchanged from R13)
// =====================================================================
#define KA_AHI 0
#define KA_ALO (KA_AHI + 128*AP)
#define KA_WT  (KA_ALO + 128*AP)
#define KA_SG  (KA_WT  + 128*AP)
#define KA_SB  (KA_SG + 128)
#define KA_WB  (KA_SB + 128)
#define SMEM_A ((KA_WB + 512) * 4)

__global__ __launch_bounds__(1024, 1) void kA(
    const float* __restrict__ x,   const float* __restrict__ lng,
    const float* __restrict__ lnb, const float* __restrict__ wb,
    const float* __restrict__ bg)
{
    extern __shared__ float sm[];
    float* ahi_f = sm + KA_AHI;
    float* alo_f = sm + KA_ALO;
    float* sg    = sm + KA_SG;
    float* sb    = sm + KA_SB;
    float* wbs   = sm + KA_WB;
    uint32_t* ahi = (uint32_t*)ahi_f;
    uint32_t* alo = (uint32_t*)alo_f;
    uint32_t* wt  = (uint32_t*)(sm + KA_WT);

    int tid = threadIdx.x, lane = tid & 31, w = tid >> 5;
    int g2 = lane >> 2, cq = lane & 3;
    int rw = w & 7, nc = w >> 3;
    int colbase = nc * 32;
    int Rb = blockIdx.x * 128;

    if (tid < 128) { sg[tid] = lng[tid]; sb[tid] = lnb[tid]; }
    if (tid >= 128 && tid < 640) wbs[tid - 128] = wb[tid - 128];

    // ---- layernorm: 8 threads per row (16 elems each) ----
    int row = tid >> 3, sub = tid & 7;
    float xv[16];
    const float* xr = x + (size_t)(Rb + row) * CDIM + sub * 16;
    #pragma unroll
    for (int m4 = 0; m4 < 4; m4++) {
        float4 t = *(const float4*)(xr + m4 * 4);
        xv[m4*4+0] = t.x; xv[m4*4+1] = t.y; xv[m4*4+2] = t.z; xv[m4*4+3] = t.w;
    }
    float sum = 0.f, sq = 0.f;
    #pragma unroll
    for (int m = 0; m < 16; m++) { sum += xv[m]; sq += xv[m]*xv[m]; }
    #pragma unroll
    for (int off = 4; off >= 1; off >>= 1) {
        sum += __shfl_xor_sync(0xffffffffu, sum, off, 8);
        sq  += __shfl_xor_sync(0xffffffffu, sq,  off, 8);
    }
    float mu = sum * (1.f / CDIM);
    float rs = rsqrtf(sq * (1.f / CDIM) - mu * mu + 1e-5f);

    __syncthreads();   // sg/sb/wbs ready
    #pragma unroll
    for (int m = 0; m < 16; m++) {
        int c = sub * 16 + m;
        float val = (xv[m] - mu) * rs * sg[c] + sb[c];
        uint32_t hb = f2tf(val);
        ahi[row * AP + c] = hb;
        alo[row * AP + c] = f2tf(val - __uint_as_float(hb));
    }
    __syncthreads();   // A ready

    // ---- triangle bias: 512 items on first 512 threads ----
    if (tid < 512) {
        int r = tid >> 2, h2 = tid & 3;
        float acc = 0.f;
        #pragma unroll 8
        for (int kk = 0; kk < CDIM; kk++)
            acc += (ahi_f[r * AP + kk] + alo_f[r * AP + kk]) * wbs[kk * NH + h2];
        g_bias[(size_t)h2 * NN + Rb + r] = acc;
    }

    // ---- 4 projection chunks ----
    int r0 = (rw << 4) + g2;
    int R0 = Rb + r0, R1 = R0 + 8;
    int i0 = R0 / NRES, j0 = R0 - i0 * NRES;
    int i1 = R1 / NRES, j1 = R1 - i1 * NRES;

    #pragma unroll 1
    for (int s = 0; s < 4; s++) {
        const uint4* src = (const uint4*)(g_wt + s * 16384);
        #pragma unroll
        for (int i = 0; i < 4; i++) {
            int idx4 = tid + i * 1024;
            int n = idx4 >> 5, k4 = idx4 & 31;
            uint4 vv = __ldg(&src[idx4]);
            *(uint4*)&wt[n * AP + k4 * 4] = vv;
        }
        __syncthreads();

        float acc[4][4];
        #pragma unroll
        for (int t = 0; t < 4; t++)
            #pragma unroll
            for (int e = 0; e < 4; e++) acc[t][e] = 0.f;

        #pragma unroll 4
        for (int ks = 0; ks < 16; ks++) {
            int kc = ks * 8;
            uint32_t h0 = ahi[r0 * AP + kc + cq];
            uint32_t h1 = ahi[(r0 + 8) * AP + kc + cq];
            uint32_t h2_ = ahi[r0 * AP + kc + cq + 4];
            uint32_t h3 = ahi[(r0 + 8) * AP + kc + cq + 4];
            if (s != 3) {
                uint32_t l0 = alo[r0 * AP + kc + cq];
                uint32_t l1 = alo[(r0 + 8) * AP + kc + cq];
                uint32_t l2 = alo[r0 * AP + kc + cq + 4];
                uint32_t l3 = alo[(r0 + 8) * AP + kc + cq + 4];
                #pragma unroll
                for (int t = 0; t < 4; t++) {
                    int n0 = (colbase + t * 8 + g2) * AP + kc;
                    uint32_t b0 = wt[n0 + cq];
                    uint32_t b1 = wt[n0 + cq + 4];
                    mma_tf32(acc[t], h0, h1, h2_, h3, b0, b1);
                    mma_tf32(acc[t], l0, l1, l2, l3, b0, b1);
                }
            } else {
                #pragma unroll
                for (int t = 0; t < 4; t++) {
                    int n0 = (colbase + t * 8 + g2) * AP + kc;
                    uint32_t b0 = wt[n0 + cq];
                    uint32_t b1 = wt[n0 + cq + 4];
                    mma_tf32(acc[t], h0, h1, h2_, h3, b0, b1);
                }
            }
        }

        if (s == 0) {
            #pragma unroll
            for (int t = 0; t < 4; t++)
                #pragma unroll
                for (int e = 0; e < 4; e++) acc[t][e] *= 0.17677669529663687f;
        }
        if (s == 3) {
            #pragma unroll
            for (int t = 0; t < 4; t++) {
                int col = colbase + t * 8 + cq * 2;
                float2 bgv = __ldg((const float2*)&bg[col]);
                acc[t][0] = 1.f / (1.f + __expf(-(acc[t][0] + bgv.x)));
                acc[t][1] = 1.f / (1.f + __expf(-(acc[t][1] + bgv.y)));
                acc[t][2] = 1.f / (1.f + __expf(-(acc[t][2] + bgv.x)));
                acc[t][3] = 1.f / (1.f + __expf(-(acc[t][3] + bgv.y)));
            }
        }
        float* dst = (s == 0) ? g_q : (s == 1) ? g_k : (s == 2) ? g_v : g_gate;
        #pragma unroll
        for (int t = 0; t < 4; t++) {
            int col = colbase + t * 8 + cq * 2;
            int h = col >> 5, d = col & 31;
            *(float2*)&dst[(((size_t)i0 * NH + h) * NRES + j0) * DH + d] =
                make_float2(acc[t][0], acc[t][1]);
            *(float2*)&dst[(((size_t)i1 * NH + h) * NRES + j1) * DH + d] =
                make_float2(acc[t][2], acc[t][3]);
        }
        __syncthreads();
    }
}

// =====================================================================
// Kernel B: attention per (i,h), tf32 mma, 320 thr = 10 warps.
// Flash-style: warp owns 16 q rows x full 320 kj (two 160-halves with
// online softmax). Zero cross-warp coupling -> no barriers in main loop.
// =====================================================================
#define KS_OFF    0
#define VS_OFF    (KS_OFF + 320*36)
#define PS_OFF    (VS_OFF + 320*36)            // 10 warps x [16][164]
#define MSK_OFF   (PS_OFF + 10*16*164)
#define SMEM_B    ((MSK_OFF + 320) * 4)

__global__ __launch_bounds__(320, 1) void kB(const float* __restrict__ mask)
{
    extern __shared__ float sm[];
    uint32_t* ksu = (uint32_t*)(sm + KS_OFF);
    uint32_t* vsu = (uint32_t*)(sm + VS_OFF);
    uint32_t* psu = (uint32_t*)(sm + PS_OFF);
    float* msk   = sm + MSK_OFF;

    int i = blockIdx.x, h = blockIdx.y;
    int tid = threadIdx.x, lane = tid & 31, w = tid >> 5;
    int g = lane >> 2, c = lane & 3;

    size_t base = ((size_t)i * NH + h) * (NRES * DH);
    const float* kg = g_k    + base;
    const float* qg = g_q    + base;
    const float* vg = g_v    + base;
    const float* gg = g_gate + base;

    for (int idx = tid; idx < NRES * DH; idx += 320) {
        int kk = idx >> 5, d = idx & 31;
        ksu[kk * 36 + d] = f2tf(kg[idx]);
        vsu[kk * 36 + d] = f2tf(vg[idx]);
    }
    for (int idx = tid; idx < NRES; idx += 320)
        msk[idx] = 1.0e9f * (mask[(size_t)i * NRES + idx] - 1.f);

    const float* bias_h = g_bias + (size_t)h * NN;
    uint32_t* pw = psu + w * 16 * 164;

    __syncthreads();

    #pragma unroll 1
    for (int p = 0; p < 2; p++) {
        int qbase = p * 160 + w * 16;
        int row0 = qbase + g, row1 = row0 + 8;

        float o[4][4];
        #pragma unroll
        for (int t = 0; t < 4; t++)
            #pragma unroll
            for (int e = 0; e < 4; e++) o[t][e] = 0.f;
        float mA = -1e30f, mB = -1e30f, lA = 0.f, lB = 0.f;

        #pragma unroll 1
        for (int half = 0; half < 2; half++) {
            int khalf = half * 160;

            // ---- S = Q_rows x K_half^T ----
            float s[20][4];
            #pragma unroll
            for (int t = 0; t < 20; t++)
                #pragma unroll
                for (int e = 0; e < 4; e++) s[t][e] = 0.f;

            #pragma unroll
            for (int ds = 0; ds < 4; ds++) {
                int dc = ds * 8;
                const float* q0 = &qg[row0 * DH + dc];
                const float* q1 = &qg[row1 * DH + dc];
                uint32_t a0 = f2tf(__ldg(q0 + c));
                uint32_t a1 = f2tf(__ldg(q1 + c));
                uint32_t a2 = f2tf(__ldg(q0 + c + 4));
                uint32_t a3 = f2tf(__ldg(q1 + c + 4));
                #pragma unroll
                for (int t = 0; t < 20; t++) {
                    int n0 = (khalf + t * 8 + g) * 36 + dc;
                    uint32_t b0 = ksu[n0 + c];
                    uint32_t b1 = ksu[n0 + c + 4];
                    mma_tf32(s[t], a0, a1, a2, a3, b0, b1);
                }
            }

            // ---- bias + mask ----
            #pragma unroll
            for (int t = 0; t < 20; t++) {
                int col = khalf + t * 8 + c * 2;
                float2 mk = *(const float2*)&msk[col];
                float2 bA = __ldg((const float2*)&bias_h[(size_t)row0 * NRES + col]);
                float2 bB = __ldg((const float2*)&bias_h[(size_t)row1 * NRES + col]);
                s[t][0] += bA.x + mk.x;  s[t][1] += bA.y + mk.y;
                s[t][2] += bB.x + mk.x;  s[t][3] += bB.y + mk.y;
            }

            // ---- online softmax update ----
            float hA = -1e30f, hB = -1e30f;
            #pragma unroll
            for (int t = 0; t < 20; t++) {
                hA = fmaxf(hA, fmaxf(s[t][0], s[t][1]));
                hB = fmaxf(hB, fmaxf(s[t][2], s[t][3]));
            }
            hA = fmaxf(hA, __shfl_xor_sync(0xffffffffu, hA, 1));
            hB = fmaxf(hB, __shfl_xor_sync(0xffffffffu, hB, 1));
            hA = fmaxf(hA, __shfl_xor_sync(0xffffffffu, hA, 2));
            hB = fmaxf(hB, __shfl_xor_sync(0xffffffffu, hB, 2));

            float nmA = fmaxf(mA, hA), nmB = fmaxf(mB, hB);
            float aA = __expf(mA - nmA), aB = __expf(mB - nmB);

            float sumA = 0.f, sumB = 0.f;
            #pragma unroll
            for (int t = 0; t < 20; t++) {
                s[t][0] = __expf(s[t][0] - nmA); sumA += s[t][0];
                s[t][1] = __expf(s[t][1] - nmA); sumA += s[t][1];
                s[t][2] = __expf(s[t][2] - nmB); sumB += s[t][2];
                s[t][3] = __expf(s[t][3] - nmB); sumB += s[t][3];
            }
            sumA += __shfl_xor_sync(0xffffffffu, sumA, 1);
            sumB += __shfl_xor_sync(0xffffffffu, sumB, 1);
            sumA += __shfl_xor_sync(0xffffffffu, sumA, 2);
            sumB += __shfl_xor_sync(0xffffffffu, sumB, 2);

            lA = lA * aA + sumA;  mA = nmA;
            lB = lB * aB + sumB;  mB = nmB;

            // rescale existing O
            #pragma unroll
            for (int t = 0; t < 4; t++) {
                o[t][0] *= aA; o[t][1] *= aA;
                o[t][2] *= aB; o[t][3] *= aB;
            }

            // ---- P (unnormalized exp, tf32) to per-warp smem ----
            #pragma unroll
            for (int t = 0; t < 20; t++) {
                int kl = t * 8 + c * 2;
                *(uint2*)&pw[g * 164 + kl] =
                    make_uint2(f2tf(s[t][0]), f2tf(s[t][1]));
                *(uint2*)&pw[(g + 8) * 164 + kl] =
                    make_uint2(f2tf(s[t][2]), f2tf(s[t][3]));
            }
            __syncwarp();

            // ---- O += P x V_half ----
            #pragma unroll 4
            for (int ks = 0; ks < 20; ks++) {
                int kc = ks * 8;
                uint32_t a0 = pw[g * 164 + kc + c];
                uint32_t a1 = pw[(g + 8) * 164 + kc + c];
                uint32_t a2 = pw[g * 164 + kc + c + 4];
                uint32_t a3 = pw[(g + 8) * 164 + kc + c + 4];
                int vr0 = (khalf + kc + c) * 36;
                int vr1 = (khalf + kc + c + 4) * 36;
                #pragma unroll
                for (int t = 0; t < 4; t++) {
                    uint32_t b0 = vsu[vr0 + t * 8 + g];
                    uint32_t b1 = vsu[vr1 + t * 8 + g];
                    mma_tf32(o[t], a0, a1, a2, a3, b0, b1);
                }
            }
            __syncwarp();   // protect pw reuse by next half
        }

        // ---- normalize + gate + store ----
        float invA = 1.f / lA, invB = 1.f / lB;
        #pragma unroll
        for (int t = 0; t < 4; t++) {
            int col = t * 8 + c * 2;
            float2 gA = __ldg((const float2*)&gg[row0 * 32 + col]);
            float2 gB = __ldg((const float2*)&gg[row1 * 32 + col]);
            float2 rA = make_float2(o[t][0] * invA * gA.x, o[t][1] * invA * gA.y);
            float2 rB = make_float2(o[t][2] * invB * gB.x, o[t][3] * invB * gB.y);
            *(float2*)&g_og[((size_t)i * NRES + row0) * CDIM + h * DH + col] = rA;
            *(float2*)&g_og[((size_t)i * NRES + row1) * CDIM + h * DH + col] = rB;
        }
    }
}

// =====================================================================
// Kernel C (tensor, 1024 thr): out = og @ wo + bo. (unchanged)
// =====================================================================
#define KC_A  0
#define KC_WT (KC_A + 128*AP)
#define SMEM_C ((KC_WT + 128*AP) * 4)

__global__ __launch_bounds__(1024, 1) void kC(
    const float* __restrict__ bo, float* __restrict__ out)
{
    extern __shared__ float sm[];
    uint32_t* ao = (uint32_t*)(sm + KC_A);
    uint32_t* wt = (uint32_t*)(sm + KC_WT);

    int tid = threadIdx.x, lane = tid & 31, w = tid >> 5;
    int g2 = lane >> 2, cq = lane & 3;
    int rw = w & 7, nc = w >> 3;
    int colbase = nc * 32;
    int Rb = blockIdx.x * 128;

    const uint4* wsrc = (const uint4*)(g_wt + 4 * 16384);
    const float4* asrc = (const float4*)(g_og + (size_t)Rb * CDIM);
    #pragma unroll
    for (int i = 0; i < 4; i++) {
        int idx4 = tid + i * 1024;
        int n = idx4 >> 5, k4 = idx4 & 31;
        uint4 wv = __ldg(&wsrc[idx4]);
        *(uint4*)&wt[n * AP + k4 * 4] = wv;
        float4 av = asrc[idx4];
        uint4 at;
        at.x = f2tf(av.x); at.y = f2tf(av.y); at.z = f2tf(av.z); at.w = f2tf(av.w);
        *(uint4*)&ao[n * AP + k4 * 4] = at;
    }
    __syncthreads();

    int r0 = (rw << 4) + g2;

    float acc[4][4];
    #pragma unroll
    for (int t = 0; t < 4; t++)
        #pragma unroll
        for (int e = 0; e < 4; e++) acc[t][e] = 0.f;

    #pragma unroll 4
    for (int ks = 0; ks < 16; ks++) {
        int kc = ks * 8;
        uint32_t a0 = ao[r0 * AP + kc + cq];
        uint32_t a1 = ao[(r0 + 8) * AP + kc + cq];
        uint32_t a2 = ao[r0 * AP + kc + cq + 4];
        uint32_t a3 = ao[(r0 + 8) * AP + kc + cq + 4];
        #pragma unroll
        for (int t = 0; t < 4; t++) {
            int n0 = (colbase + t * 8 + g2) * AP + kc;
            uint32_t b0 = wt[n0 + cq];
            uint32_t b1 = wt[n0 + cq + 4];
            mma_tf32(acc[t], a0, a1, a2, a3, b0, b1);
        }
    }

    #pragma unroll
    for (int t = 0; t < 4; t++) {
        int col = colbase + t * 8 + cq * 2;
        float2 bb = __ldg((const float2*)&bo[col]);
        *(float2*)&out[(size_t)(Rb + r0) * CDIM + col] =
            make_float2(acc[t][0] + bb.x, acc[t][1] + bb.y);
        *(float2*)&out[(size_t)(Rb + r0 + 8) * CDIM + col] =
            make_float2(acc[t][2] + bb.x, acc[t][3] + bb.y);
    }
}

// =====================================================================
extern "C" void kernel_launch(void* const* d_in, const int* in_sizes, int n_in,
                              void* d_out, int out_size)
{
    const float* x    = (const float*)d_in[0];
    const float* mask = (const float*)d_in[1];
    const float* lng  = (const float*)d_in[2];
    const float* lnb  = (const float*)d_in[3];
    const float* wb   = (const float*)d_in[4];
    const float* wq   = (const float*)d_in[5];
    const float* wk   = (const float*)d_in[6];
    const float* wv   = (const float*)d_in[7];
    const float* wg   = (const float*)d_in[8];
    const float* bg   = (const float*)d_in[9];
    const float* wo   = (const float*)d_in[10];
    const float* bo   = (const float*)d_in[11];
    float* out = (float*)d_out;

    cudaFuncSetAttribute(kA, cudaFuncAttributeMaxDynamicSharedMemorySize, SMEM_A);
    cudaFuncSetAttribute(kB, cudaFuncAttributeMaxDynamicSharedMemorySize, SMEM_B);
    cudaFuncSetAttribute(kC, cudaFuncAttributeMaxDynamicSharedMemorySize, SMEM_C);

    kW<<<320, 256>>>(wq, wk, wv, wg, wo);
    kA<<<NN / 128, 1024, SMEM_A>>>(x, lng, lnb, wb, bg);
    kB<<<dim3(NRES, NH), 320, SMEM_B>>>(mask);
    kC<<<NN / 128, 1024, SMEM_C>>>(bo, out);
}

// round 15
// speedup vs baseline: 2.2342x; 1.1520x over previous
#include <cuda_runtime.h>
#include <cstdint>

#define NRES 320
#define CDIM 128
#define NH 4
#define DH 32
#define NN (NRES*NRES)
#define AP 132   // padded row stride for MMA smem tiles

// ---------- tf32 mma helpers (kA/kC) ----------
__device__ __forceinline__ uint32_t f2tf(float f) {
    uint32_t u; asm("cvt.rna.tf32.f32 %0, %1;" : "=r"(u) : "f"(f)); return u;
}
__device__ __forceinline__ void mma_tf32(float* d,
    uint32_t a0, uint32_t a1, uint32_t a2, uint32_t a3,
    uint32_t b0, uint32_t b1)
{
    asm volatile(
        "mma.sync.aligned.m16n8k8.row.col.f32.tf32.tf32.f32 "
        "{%0,%1,%2,%3}, {%4,%5,%6,%7}, {%8,%9}, {%0,%1,%2,%3};"
        : "+f"(d[0]), "+f"(d[1]), "+f"(d[2]), "+f"(d[3])
        : "r"(a0), "r"(a1), "r"(a2), "r"(a3), "r"(b0), "r"(b1));
}

// ---------- fp16 mma helpers (kB) ----------
__device__ __forceinline__ uint32_t f2h2(float lo, float hi) {
    uint32_t r; asm("cvt.rn.f16x2.f32 %0, %1, %2;" : "=r"(r) : "f"(hi), "f"(lo));
    return r;
}
__device__ __forceinline__ void mma_f16(float* d,
    uint32_t a0, uint32_t a1, uint32_t a2, uint32_t a3,
    uint32_t b0, uint32_t b1)
{
    asm volatile(
        "mma.sync.aligned.m16n8k16.row.col.f32.f16.f16.f32 "
        "{%0,%1,%2,%3}, {%4,%5,%6,%7}, {%8,%9}, {%0,%1,%2,%3};"
        : "+f"(d[0]), "+f"(d[1]), "+f"(d[2]), "+f"(d[3])
        : "r"(a0), "r"(a1), "r"(a2), "r"(a3), "r"(b0), "r"(b1));
}

// -------- device scratch --------
__device__ float g_q   [(size_t)NRES*NH*NRES*DH];   // [i][h][j][d]
__device__ float g_k   [(size_t)NRES*NH*NRES*DH];
__device__ float g_v   [(size_t)NRES*NH*NRES*DH];
__device__ float g_gate[(size_t)NRES*NH*NRES*DH];
__device__ float g_og  [(size_t)NN*CDIM];
__device__ float g_bias[(size_t)NH*NN];             // [h][q][j]
__device__ uint32_t g_wt[5*128*128];                // transposed tf32 weights [s][n][k]

// =====================================================================
// Kernel W: one-shot transpose+convert of the 5 weight matrices.
// =====================================================================
__global__ __launch_bounds__(256, 4) void kW(
    const float* __restrict__ wq, const float* __restrict__ wk,
    const float* __restrict__ wv, const float* __restrict__ wg,
    const float* __restrict__ wo)
{
    int idx = blockIdx.x * 256 + threadIdx.x;    // 5*16384 total
    int s = idx >> 14, r = idx & 16383;
    int n = r >> 7, k = r & 127;
    const float* W = (s == 0) ? wq : (s == 1) ? wk : (s == 2) ? wv
                   : (s == 3) ? wg : wo;
    g_wt[idx] = f2tf(W[k * 128 + n]);
}

// =====================================================================
// Kernel A (tensor, 1024 thr): LN + q/k/v/gate projections + tri bias.
// (unchanged from R14)
// =====================================================================
#define KA_AHI 0
#define KA_ALO (KA_AHI + 128*AP)
#define KA_WT  (KA_ALO + 128*AP)
#define KA_SG  (KA_WT  + 128*AP)
#define KA_SB  (KA_SG + 128)
#define KA_WB  (KA_SB + 128)
#define SMEM_A ((KA_WB + 512) * 4)

__global__ __launch_bounds__(1024, 1) void kA(
    const float* __restrict__ x,   const float* __restrict__ lng,
    const float* __restrict__ lnb, const float* __restrict__ wb,
    const float* __restrict__ bg)
{
    extern __shared__ float sm[];
    float* ahi_f = sm + KA_AHI;
    float* alo_f = sm + KA_ALO;
    float* sg    = sm + KA_SG;
    float* sb    = sm + KA_SB;
    float* wbs   = sm + KA_WB;
    uint32_t* ahi = (uint32_t*)ahi_f;
    uint32_t* alo = (uint32_t*)alo_f;
    uint32_t* wt  = (uint32_t*)(sm + KA_WT);

    int tid = threadIdx.x, lane = tid & 31, w = tid >> 5;
    int g2 = lane >> 2, cq = lane & 3;
    int rw = w & 7, nc = w >> 3;
    int colbase = nc * 32;
    int Rb = blockIdx.x * 128;

    if (tid < 128) { sg[tid] = lng[tid]; sb[tid] = lnb[tid]; }
    if (tid >= 128 && tid < 640) wbs[tid - 128] = wb[tid - 128];

    int row = tid >> 3, sub = tid & 7;
    float xv[16];
    const float* xr = x + (size_t)(Rb + row) * CDIM + sub * 16;
    #pragma unroll
    for (int m4 = 0; m4 < 4; m4++) {
        float4 t = *(const float4*)(xr + m4 * 4);
        xv[m4*4+0] = t.x; xv[m4*4+1] = t.y; xv[m4*4+2] = t.z; xv[m4*4+3] = t.w;
    }
    float sum = 0.f, sq = 0.f;
    #pragma unroll
    for (int m = 0; m < 16; m++) { sum += xv[m]; sq += xv[m]*xv[m]; }
    #pragma unroll
    for (int off = 4; off >= 1; off >>= 1) {
        sum += __shfl_xor_sync(0xffffffffu, sum, off, 8);
        sq  += __shfl_xor_sync(0xffffffffu, sq,  off, 8);
    }
    float mu = sum * (1.f / CDIM);
    float rs = rsqrtf(sq * (1.f / CDIM) - mu * mu + 1e-5f);

    __syncthreads();
    #pragma unroll
    for (int m = 0; m < 16; m++) {
        int c = sub * 16 + m;
        float val = (xv[m] - mu) * rs * sg[c] + sb[c];
        uint32_t hb = f2tf(val);
        ahi[row * AP + c] = hb;
        alo[row * AP + c] = f2tf(val - __uint_as_float(hb));
    }
    __syncthreads();

    if (tid < 512) {
        int r = tid >> 2, h2 = tid & 3;
        float acc = 0.f;
        #pragma unroll 8
        for (int kk = 0; kk < CDIM; kk++)
            acc += (ahi_f[r * AP + kk] + alo_f[r * AP + kk]) * wbs[kk * NH + h2];
        g_bias[(size_t)h2 * NN + Rb + r] = acc;
    }

    int r0 = (rw << 4) + g2;
    int R0 = Rb + r0, R1 = R0 + 8;
    int i0 = R0 / NRES, j0 = R0 - i0 * NRES;
    int i1 = R1 / NRES, j1 = R1 - i1 * NRES;

    #pragma unroll 1
    for (int s = 0; s < 4; s++) {
        const uint4* src = (const uint4*)(g_wt + s * 16384);
        #pragma unroll
        for (int i = 0; i < 4; i++) {
            int idx4 = tid + i * 1024;
            int n = idx4 >> 5, k4 = idx4 & 31;
            uint4 vv = __ldg(&src[idx4]);
            *(uint4*)&wt[n * AP + k4 * 4] = vv;
        }
        __syncthreads();

        float acc[4][4];
        #pragma unroll
        for (int t = 0; t < 4; t++)
            #pragma unroll
            for (int e = 0; e < 4; e++) acc[t][e] = 0.f;

        #pragma unroll 4
        for (int ks = 0; ks < 16; ks++) {
            int kc = ks * 8;
            uint32_t h0 = ahi[r0 * AP + kc + cq];
            uint32_t h1 = ahi[(r0 + 8) * AP + kc + cq];
            uint32_t h2_ = ahi[r0 * AP + kc + cq + 4];
            uint32_t h3 = ahi[(r0 + 8) * AP + kc + cq + 4];
            if (s != 3) {
                uint32_t l0 = alo[r0 * AP + kc + cq];
                uint32_t l1 = alo[(r0 + 8) * AP + kc + cq];
                uint32_t l2 = alo[r0 * AP + kc + cq + 4];
                uint32_t l3 = alo[(r0 + 8) * AP + kc + cq + 4];
                #pragma unroll
                for (int t = 0; t < 4; t++) {
                    int n0 = (colbase + t * 8 + g2) * AP + kc;
                    uint32_t b0 = wt[n0 + cq];
                    uint32_t b1 = wt[n0 + cq + 4];
                    mma_tf32(acc[t], h0, h1, h2_, h3, b0, b1);
                    mma_tf32(acc[t], l0, l1, l2, l3, b0, b1);
                }
            } else {
                #pragma unroll
                for (int t = 0; t < 4; t++) {
                    int n0 = (colbase + t * 8 + g2) * AP + kc;
                    uint32_t b0 = wt[n0 + cq];
                    uint32_t b1 = wt[n0 + cq + 4];
                    mma_tf32(acc[t], h0, h1, h2_, h3, b0, b1);
                }
            }
        }

        if (s == 0) {
            #pragma unroll
            for (int t = 0; t < 4; t++)
                #pragma unroll
                for (int e = 0; e < 4; e++) acc[t][e] *= 0.17677669529663687f;
        }
        if (s == 3) {
            #pragma unroll
            for (int t = 0; t < 4; t++) {
                int col = colbase + t * 8 + cq * 2;
                float2 bgv = __ldg((const float2*)&bg[col]);
                acc[t][0] = 1.f / (1.f + __expf(-(acc[t][0] + bgv.x)));
                acc[t][1] = 1.f / (1.f + __expf(-(acc[t][1] + bgv.y)));
                acc[t][2] = 1.f / (1.f + __expf(-(acc[t][2] + bgv.x)));
                acc[t][3] = 1.f / (1.f + __expf(-(acc[t][3] + bgv.y)));
            }
        }
        float* dst = (s == 0) ? g_q : (s == 1) ? g_k : (s == 2) ? g_v : g_gate;
        #pragma unroll
        for (int t = 0; t < 4; t++) {
            int col = colbase + t * 8 + cq * 2;
            int h = col >> 5, d = col & 31;
            *(float2*)&dst[(((size_t)i0 * NH + h) * NRES + j0) * DH + d] =
                make_float2(acc[t][0], acc[t][1]);
            *(float2*)&dst[(((size_t)i1 * NH + h) * NRES + j1) * DH + d] =
                make_float2(acc[t][2], acc[t][3]);
        }
        __syncthreads();
    }
}

// =====================================================================
// Kernel B: attention per (i,h), fp16 m16n8k16 mma, 256 thr, 2 blk/SM.
// Flash online softmax; warp owns 16 q x 320 kj (two 160-halves).
// K fp16 [kj][40h], V^T fp16 [d][328h], P fp16 [16][168h] per warp.
// =====================================================================
#define KS_OFF    0                            // 320*20 words
#define VS_OFF    (KS_OFF + 6400)              // 32*164 words
#define PS_OFF    (VS_OFF + 5248)              // 8 warps * 16*84 words
#define MSK_OFF   (PS_OFF + 10752)
#define SMEM_B    ((MSK_OFF + 320) * 4)

__global__ __launch_bounds__(256, 2) void kB(const float* __restrict__ mask)
{
    extern __shared__ float sm[];
    uint32_t* ksu = (uint32_t*)(sm + KS_OFF);   // word-indexed half2
    uint32_t* vsu = (uint32_t*)(sm + VS_OFF);
    uint32_t* psu = (uint32_t*)(sm + PS_OFF);
    float* msk   = sm + MSK_OFF;

    int i = blockIdx.x, h = blockIdx.y;
    int tid = threadIdx.x, lane = tid & 31, w = tid >> 5;
    int g = lane >> 2, c = lane & 3;

    size_t base = ((size_t)i * NH + h) * (NRES * DH);
    const float* kg = g_k    + base;
    const float* qg = g_q    + base;
    const float* vg = g_v    + base;
    const float* gg = g_gate + base;

    // stage K as fp16 [kj][20 words]
    for (int idx = tid; idx < 5120; idx += 256) {
        int kk = idx >> 4, d2 = idx & 15;
        float2 t = *(const float2*)&kg[kk * 32 + d2 * 2];
        ksu[kk * 20 + d2] = f2h2(t.x, t.y);
    }
    // stage V transposed as fp16 [d][164 words] (kk pairs)
    for (int idx = tid; idx < 5120; idx += 256) {
        int kkp = idx >> 5, d = idx & 31;
        float v0 = vg[(2 * kkp) * 32 + d];
        float v1 = vg[(2 * kkp + 1) * 32 + d];
        vsu[d * 164 + kkp] = f2h2(v0, v1);
    }
    for (int idx = tid; idx < NRES; idx += 256)
        msk[idx] = 1.0e9f * (mask[(size_t)i * NRES + idx] - 1.f);

    const float* bias_h = g_bias + (size_t)h * NN;
    uint32_t* pw = psu + w * 1344;   // 16*84 words per warp

    __syncthreads();

    #pragma unroll 1
    for (int p = 0; p < 3; p++) {
        int tile = p * 8 + w;
        if (tile >= 20) break;
        int row0 = tile * 16 + g, row1 = row0 + 8;

        // q fragments (fp16), reused across both halves
        uint32_t qa[2][4];
        #pragma unroll
        for (int ds = 0; ds < 2; ds++) {
            float2 t0 = __ldg((const float2*)&qg[row0 * DH + 16 * ds + 2 * c]);
            float2 t1 = __ldg((const float2*)&qg[row1 * DH + 16 * ds + 2 * c]);
            float2 t2 = __ldg((const float2*)&qg[row0 * DH + 16 * ds + 2 * c + 8]);
            float2 t3 = __ldg((const float2*)&qg[row1 * DH + 16 * ds + 2 * c + 8]);
            qa[ds][0] = f2h2(t0.x, t0.y);
            qa[ds][1] = f2h2(t1.x, t1.y);
            qa[ds][2] = f2h2(t2.x, t2.y);
            qa[ds][3] = f2h2(t3.x, t3.y);
        }

        float o[4][4];
        #pragma unroll
        for (int t = 0; t < 4; t++)
            #pragma unroll
            for (int e = 0; e < 4; e++) o[t][e] = 0.f;
        float mA = -1e30f, mB = -1e30f, lA = 0.f, lB = 0.f;

        #pragma unroll 1
        for (int half = 0; half < 2; half++) {
            int khalf = half * 160;

            // ---- S = Q x K^T (fp16, K=16 per MMA) ----
            float s[20][4];
            #pragma unroll
            for (int t = 0; t < 20; t++)
                #pragma unroll
                for (int e = 0; e < 4; e++) s[t][e] = 0.f;

            #pragma unroll
            for (int ds = 0; ds < 2; ds++) {
                #pragma unroll
                for (int t = 0; t < 20; t++) {
                    int kr = (khalf + t * 8 + g) * 20 + 8 * ds + c;
                    uint32_t b0 = ksu[kr];
                    uint32_t b1 = ksu[kr + 4];
                    mma_f16(s[t], qa[ds][0], qa[ds][1], qa[ds][2], qa[ds][3], b0, b1);
                }
            }

            // ---- bias + mask ----
            #pragma unroll
            for (int t = 0; t < 20; t++) {
                int col = khalf + t * 8 + c * 2;
                float2 mk = *(const float2*)&msk[col];
                float2 bA = __ldg((const float2*)&bias_h[(size_t)row0 * NRES + col]);
                float2 bB = __ldg((const float2*)&bias_h[(size_t)row1 * NRES + col]);
                s[t][0] += bA.x + mk.x;  s[t][1] += bA.y + mk.y;
                s[t][2] += bB.x + mk.x;  s[t][3] += bB.y + mk.y;
            }

            // ---- online softmax update ----
            float hA = -1e30f, hB = -1e30f;
            #pragma unroll
            for (int t = 0; t < 20; t++) {
                hA = fmaxf(hA, fmaxf(s[t][0], s[t][1]));
                hB = fmaxf(hB, fmaxf(s[t][2], s[t][3]));
            }
            hA = fmaxf(hA, __shfl_xor_sync(0xffffffffu, hA, 1));
            hB = fmaxf(hB, __shfl_xor_sync(0xffffffffu, hB, 1));
            hA = fmaxf(hA, __shfl_xor_sync(0xffffffffu, hA, 2));
            hB = fmaxf(hB, __shfl_xor_sync(0xffffffffu, hB, 2));

            float nmA = fmaxf(mA, hA), nmB = fmaxf(mB, hB);
            float aA = __expf(mA - nmA), aB = __expf(mB - nmB);

            float sumA = 0.f, sumB = 0.f;
            #pragma unroll
            for (int t = 0; t < 20; t++) {
                s[t][0] = __expf(s[t][0] - nmA); sumA += s[t][0];
                s[t][1] = __expf(s[t][1] - nmA); sumA += s[t][1];
                s[t][2] = __expf(s[t][2] - nmB); sumB += s[t][2];
                s[t][3] = __expf(s[t][3] - nmB); sumB += s[t][3];
            }
            sumA += __shfl_xor_sync(0xffffffffu, sumA, 1);
            sumB += __shfl_xor_sync(0xffffffffu, sumB, 1);
            sumA += __shfl_xor_sync(0xffffffffu, sumA, 2);
            sumB += __shfl_xor_sync(0xffffffffu, sumB, 2);

            lA = lA * aA + sumA;  mA = nmA;
            lB = lB * aB + sumB;  mB = nmB;

            #pragma unroll
            for (int t = 0; t < 4; t++) {
                o[t][0] *= aA; o[t][1] *= aA;
                o[t][2] *= aB; o[t][3] *= aB;
            }

            // ---- P to fp16 smem: acc pair IS the half2 word ----
            #pragma unroll
            for (int t = 0; t < 20; t++) {
                pw[g * 84 + 4 * t + c]       = f2h2(s[t][0], s[t][1]);
                pw[(g + 8) * 84 + 4 * t + c] = f2h2(s[t][2], s[t][3]);
            }
            __syncwarp();

            // ---- O += P x V_half (fp16, K=16 per MMA) ----
            #pragma unroll 2
            for (int ks = 0; ks < 10; ks++) {
                uint32_t a0 = pw[g * 84 + 8 * ks + c];
                uint32_t a1 = pw[(g + 8) * 84 + 8 * ks + c];
                uint32_t a2 = pw[g * 84 + 8 * ks + c + 4];
                uint32_t a3 = pw[(g + 8) * 84 + 8 * ks + c + 4];
                int kbase = (khalf >> 1) + 8 * ks + c;   // kk-pair index
                #pragma unroll
                for (int t = 0; t < 4; t++) {
                    int vr = (t * 8 + g) * 164 + kbase;
                    uint32_t b0 = vsu[vr];
                    uint32_t b1 = vsu[vr + 4];
                    mma_f16(o[t], a0, a1, a2, a3, b0, b1);
                }
            }
            __syncwarp();
        }

        // ---- normalize + gate + store ----
        float invA = 1.f / lA, invB = 1.f / lB;
        #pragma unroll
        for (int t = 0; t < 4; t++) {
            int col = t * 8 + c * 2;
            float2 gA = __ldg((const float2*)&gg[row0 * 32 + col]);
            float2 gB = __ldg((const float2*)&gg[row1 * 32 + col]);
            float2 rA = make_float2(o[t][0] * invA * gA.x, o[t][1] * invA * gA.y);
            float2 rB = make_float2(o[t][2] * invB * gB.x, o[t][3] * invB * gB.y);
            *(float2*)&g_og[((size_t)i * NRES + row0) * CDIM + h * DH + col] = rA;
            *(float2*)&g_og[((size_t)i * NRES + row1) * CDIM + h * DH + col] = rB;
        }
    }
}

// =====================================================================
// Kernel C (tensor, 1024 thr): out = og @ wo + bo. (unchanged)
// =====================================================================
#define KC_A  0
#define KC_WT (KC_A + 128*AP)
#define SMEM_C ((KC_WT + 128*AP) * 4)

__global__ __launch_bounds__(1024, 1) void kC(
    const float* __restrict__ bo, float* __restrict__ out)
{
    extern __shared__ float sm[];
    uint32_t* ao = (uint32_t*)(sm + KC_A);
    uint32_t* wt = (uint32_t*)(sm + KC_WT);

    int tid = threadIdx.x, lane = tid & 31, w = tid >> 5;
    int g2 = lane >> 2, cq = lane & 3;
    int rw = w & 7, nc = w >> 3;
    int colbase = nc * 32;
    int Rb = blockIdx.x * 128;

    const uint4* wsrc = (const uint4*)(g_wt + 4 * 16384);
    const float4* asrc = (const float4*)(g_og + (size_t)Rb * CDIM);
    #pragma unroll
    for (int i = 0; i < 4; i++) {
        int idx4 = tid + i * 1024;
        int n = idx4 >> 5, k4 = idx4 & 31;
        uint4 wv = __ldg(&wsrc[idx4]);
        *(uint4*)&wt[n * AP + k4 * 4] = wv;
        float4 av = asrc[idx4];
        uint4 at;
        at.x = f2tf(av.x); at.y = f2tf(av.y); at.z = f2tf(av.z); at.w = f2tf(av.w);
        *(uint4*)&ao[n * AP + k4 * 4] = at;
    }
    __syncthreads();

    int r0 = (rw << 4) + g2;

    float acc[4][4];
    #pragma unroll
    for (int t = 0; t < 4; t++)
        #pragma unroll
        for (int e = 0; e < 4; e++) acc[t][e] = 0.f;

    #pragma unroll 4
    for (int ks = 0; ks < 16; ks++) {
        int kc = ks * 8;
        uint32_t a0 = ao[r0 * AP + kc + cq];
        uint32_t a1 = ao[(r0 + 8) * AP + kc + cq];
        uint32_t a2 = ao[r0 * AP + kc + cq + 4];
        uint32_t a3 = ao[(r0 + 8) * AP + kc + cq + 4];
        #pragma unroll
        for (int t = 0; t < 4; t++) {
            int n0 = (colbase + t * 8 + g2) * AP + kc;
            uint32_t b0 = wt[n0 + cq];
            uint32_t b1 = wt[n0 + cq + 4];
            mma_tf32(acc[t], a0, a1, a2, a3, b0, b1);
        }
    }

    #pragma unroll
    for (int t = 0; t < 4; t++) {
        int col = colbase + t * 8 + cq * 2;
        float2 bb = __ldg((const float2*)&bo[col]);
        *(float2*)&out[(size_t)(Rb + r0) * CDIM + col] =
            make_float2(acc[t][0] + bb.x, acc[t][1] + bb.y);
        *(float2*)&out[(size_t)(Rb + r0 + 8) * CDIM + col] =
            make_float2(acc[t][2] + bb.x, acc[t][3] + bb.y);
    }
}

// =====================================================================
extern "C" void kernel_launch(void* const* d_in, const int* in_sizes, int n_in,
                              void* d_out, int out_size)
{
    const float* x    = (const float*)d_in[0];
    const float* mask = (const float*)d_in[1];
    const float* lng  = (const float*)d_in[2];
    const float* lnb  = (const float*)d_in[3];
    const float* wb   = (const float*)d_in[4];
    const float* wq   = (const float*)d_in[5];
    const float* wk   = (const float*)d_in[6];
    const float* wv   = (const float*)d_in[7];
    const float* wg   = (const float*)d_in[8];
    const float* bg   = (const float*)d_in[9];
    const float* wo   = (const float*)d_in[10];
    const float* bo   = (const float*)d_in[11];
    float* out = (float*)d_out;

    cudaFuncSetAttribute(kA, cudaFuncAttributeMaxDynamicSharedMemorySize, SMEM_A);
    cudaFuncSetAttribute(kB, cudaFuncAttributeMaxDynamicSharedMemorySize, SMEM_B);
    cudaFuncSetAttribute(kC, cudaFuncAttributeMaxDynamicSharedMemorySize, SMEM_C);

    kW<<<320, 256>>>(wq, wk, wv, wg, wo);
    kA<<<NN / 128, 1024, SMEM_A>>>(x, lng, lnb, wb, bg);
    kB<<<dim3(NRES, NH), 256, SMEM_B>>>(mask);
    kC<<<NN / 128, 1024, SMEM_C>>>(bo, out);
}

// round 16
// speedup vs baseline: 2.3926x; 1.0709x over previous
#include <cuda_runtime.h>
#include <cstdint>

#define NRES 320
#define CDIM 128
#define NH 4
#define DH 32
#define NN (NRES*NRES)
#define APH 68   // padded row stride (half2 words) for fp16 MMA tiles

// ---------- fp16 mma helpers ----------
__device__ __forceinline__ uint32_t f2h2(float lo, float hi) {
    uint32_t r; asm("cvt.rn.f16x2.f32 %0, %1, %2;" : "=r"(r) : "f"(hi), "f"(lo));
    return r;
}
__device__ __forceinline__ float h2lo_f(float v) {   // fp16 rounding of v
    uint32_t u; asm("cvt.rn.f16x2.f32 %0, %1, %1;" : "=r"(u) : "f"(v));
    float r; asm("cvt.f32.f16 %0, %1;" : "=f"(r) : "h"((unsigned short)(u & 0xffff)));
    return r;
}
__device__ __forceinline__ void mma_f16(float* d,
    uint32_t a0, uint32_t a1, uint32_t a2, uint32_t a3,
    uint32_t b0, uint32_t b1)
{
    asm volatile(
        "mma.sync.aligned.m16n8k16.row.col.f32.f16.f16.f32 "
        "{%0,%1,%2,%3}, {%4,%5,%6,%7}, {%8,%9}, {%0,%1,%2,%3};"
        : "+f"(d[0]), "+f"(d[1]), "+f"(d[2]), "+f"(d[3])
        : "r"(a0), "r"(a1), "r"(a2), "r"(a3), "r"(b0), "r"(b1));
}

// -------- device scratch --------
__device__ float g_q   [(size_t)NRES*NH*NRES*DH];   // [i][h][j][d]
__device__ float g_k   [(size_t)NRES*NH*NRES*DH];
__device__ float g_v   [(size_t)NRES*NH*NRES*DH];
__device__ float g_gate[(size_t)NRES*NH*NRES*DH];
__device__ float g_og  [(size_t)NN*CDIM];
__device__ float g_bias[(size_t)NH*NN];             // [h][q][j]
__device__ uint32_t g_wh[5*128*64];                 // transposed fp16 weights [s][n][k2]

// =====================================================================
// Kernel W: one-shot transpose+convert of the 5 weight matrices (fp16).
// =====================================================================
__global__ __launch_bounds__(256, 4) void kW(
    const float* __restrict__ wq, const float* __restrict__ wk,
    const float* __restrict__ wv, const float* __restrict__ wg,
    const float* __restrict__ wo)
{
    int idx = blockIdx.x * 256 + threadIdx.x;    // 5*8192 words
    int s = idx >> 13, r = idx & 8191;
    int n = r >> 6, k2 = r & 63;
    const float* W = (s == 0) ? wq : (s == 1) ? wk : (s == 2) ? wv
                   : (s == 3) ? wg : wo;
    float w0 = W[(2 * k2) * 128 + n];
    float w1 = W[(2 * k2 + 1) * 128 + n];
    g_wh[idx] = f2h2(w0, w1);
}

// =====================================================================
// Kernel A (fp16 tensor, 1024 thr, 2 blocks/SM): LN + projections + bias.
// Split-A (hi+lo fp16) for q/k/v; single-term for gate.
// Tri-bias computed in registers (shuffle reduce), no fp32 A tile.
// =====================================================================
#define KA_AHI 0
#define KA_ALO (KA_AHI + 128*APH)
#define KA_WT  (KA_ALO + 128*APH)
#define KA_SG  (KA_WT  + 128*APH)
#define KA_SB  (KA_SG + 128)
#define KA_WB  (KA_SB + 128)
#define SMEM_A ((KA_WB + 512) * 4)

__global__ __launch_bounds__(1024, 2) void kA(
    const float* __restrict__ x,   const float* __restrict__ lng,
    const float* __restrict__ lnb, const float* __restrict__ wb,
    const float* __restrict__ bg)
{
    extern __shared__ float sm[];
    uint32_t* ahi = (uint32_t*)(sm + KA_AHI);
    uint32_t* alo = (uint32_t*)(sm + KA_ALO);
    uint32_t* wt  = (uint32_t*)(sm + KA_WT);
    float* sg  = sm + KA_SG;
    float* sb  = sm + KA_SB;
    float* wbs = sm + KA_WB;

    int tid = threadIdx.x, lane = tid & 31, w = tid >> 5;
    int g2 = lane >> 2, cq = lane & 3;
    int rw = w & 7, nc = w >> 3;
    int colbase = nc * 32;
    int Rb = blockIdx.x * 128;

    if (tid < 128) { sg[tid] = lng[tid]; sb[tid] = lnb[tid]; }
    if (tid >= 128 && tid < 640) wbs[tid - 128] = wb[tid - 128];

    // ---- layernorm: 8 threads per row (16 elems each) ----
    int row = tid >> 3, sub = tid & 7;
    float xv[16];
    const float* xr = x + (size_t)(Rb + row) * CDIM + sub * 16;
    #pragma unroll
    for (int m4 = 0; m4 < 4; m4++) {
        float4 t = *(const float4*)(xr + m4 * 4);
        xv[m4*4+0] = t.x; xv[m4*4+1] = t.y; xv[m4*4+2] = t.z; xv[m4*4+3] = t.w;
    }
    float sum = 0.f, sq = 0.f;
    #pragma unroll
    for (int m = 0; m < 16; m++) { sum += xv[m]; sq += xv[m]*xv[m]; }
    #pragma unroll
    for (int off = 4; off >= 1; off >>= 1) {
        sum += __shfl_xor_sync(0xffffffffu, sum, off, 8);
        sq  += __shfl_xor_sync(0xffffffffu, sq,  off, 8);
    }
    float mu = sum * (1.f / CDIM);
    float rs = rsqrtf(sq * (1.f / CDIM) - mu * mu + 1e-5f);

    __syncthreads();   // sg/sb/wbs ready

    // normalize, split into fp16 hi/lo half2 words, keep fp32 in xv for bias
    #pragma unroll
    for (int m2 = 0; m2 < 8; m2++) {
        int c0 = sub * 16 + 2 * m2;
        float v0 = (xv[2*m2]   - mu) * rs * sg[c0]     + sb[c0];
        float v1 = (xv[2*m2+1] - mu) * rs * sg[c0 + 1] + sb[c0 + 1];
        xv[2*m2] = v0; xv[2*m2+1] = v1;
        ahi[row * APH + sub * 8 + m2] = f2h2(v0, v1);
        alo[row * APH + sub * 8 + m2] = f2h2(v0 - h2lo_f(v0), v1 - h2lo_f(v1));
    }

    // ---- triangle bias in registers: partial dot + width-8 reduce ----
    {
        float part[4] = {0.f, 0.f, 0.f, 0.f};
        #pragma unroll
        for (int m = 0; m < 16; m++) {
            int cc = sub * 16 + m;
            float v = xv[m];
            #pragma unroll
            for (int j = 0; j < 4; j++) part[j] += v * wbs[cc * 4 + j];
        }
        #pragma unroll
        for (int off = 4; off >= 1; off >>= 1)
            #pragma unroll
            for (int j = 0; j < 4; j++)
                part[j] += __shfl_xor_sync(0xffffffffu, part[j], off, 8);
        if (sub == 0) {
            #pragma unroll
            for (int j = 0; j < 4; j++)
                g_bias[(size_t)j * NN + Rb + row] = part[j];
        }
    }
    __syncthreads();   // A tiles ready

    // ---- 4 projection chunks (fp16 MMA, K=16/step) ----
    int r0 = (rw << 4) + g2;
    int R0 = Rb + r0, R1 = R0 + 8;
    int i0 = R0 / NRES, j0 = R0 - i0 * NRES;
    int i1 = R1 / NRES, j1 = R1 - i1 * NRES;

    #pragma unroll 1
    for (int s = 0; s < 4; s++) {
        const uint4* src = (const uint4*)(g_wh + s * 8192);
        #pragma unroll
        for (int i = 0; i < 2; i++) {
            int idx4 = tid + i * 1024;          // 2048 uint4
            int n = idx4 >> 4, k4 = idx4 & 15;
            uint4 vv = __ldg(&src[idx4]);
            *(uint4*)&wt[n * APH + k4 * 4] = vv;
        }
        __syncthreads();

        float acc[4][4];
        #pragma unroll
        for (int t = 0; t < 4; t++)
            #pragma unroll
            for (int e = 0; e < 4; e++) acc[t][e] = 0.f;

        #pragma unroll 2
        for (int ks = 0; ks < 8; ks++) {
            int kc2 = ks * 8;
            uint32_t h0 = ahi[r0 * APH + kc2 + cq];
            uint32_t h1 = ahi[(r0 + 8) * APH + kc2 + cq];
            uint32_t h2_ = ahi[r0 * APH + kc2 + cq + 4];
            uint32_t h3 = ahi[(r0 + 8) * APH + kc2 + cq + 4];
            if (s != 3) {
                uint32_t l0 = alo[r0 * APH + kc2 + cq];
                uint32_t l1 = alo[(r0 + 8) * APH + kc2 + cq];
                uint32_t l2 = alo[r0 * APH + kc2 + cq + 4];
                uint32_t l3 = alo[(r0 + 8) * APH + kc2 + cq + 4];
                #pragma unroll
                for (int t = 0; t < 4; t++) {
                    int n0 = (colbase + t * 8 + g2) * APH + kc2;
                    uint32_t b0 = wt[n0 + cq];
                    uint32_t b1 = wt[n0 + cq + 4];
                    mma_f16(acc[t], h0, h1, h2_, h3, b0, b1);
                    mma_f16(acc[t], l0, l1, l2, l3, b0, b1);
                }
            } else {
                #pragma unroll
                for (int t = 0; t < 4; t++) {
                    int n0 = (colbase + t * 8 + g2) * APH + kc2;
                    uint32_t b0 = wt[n0 + cq];
                    uint32_t b1 = wt[n0 + cq + 4];
                    mma_f16(acc[t], h0, h1, h2_, h3, b0, b1);
                }
            }
        }

        if (s == 0) {
            #pragma unroll
            for (int t = 0; t < 4; t++)
                #pragma unroll
                for (int e = 0; e < 4; e++) acc[t][e] *= 0.17677669529663687f;
        }
        if (s == 3) {
            #pragma unroll
            for (int t = 0; t < 4; t++) {
                int col = colbase + t * 8 + cq * 2;
                float2 bgv = __ldg((const float2*)&bg[col]);
                acc[t][0] = 1.f / (1.f + __expf(-(acc[t][0] + bgv.x)));
                acc[t][1] = 1.f / (1.f + __expf(-(acc[t][1] + bgv.y)));
                acc[t][2] = 1.f / (1.f + __expf(-(acc[t][2] + bgv.x)));
                acc[t][3] = 1.f / (1.f + __expf(-(acc[t][3] + bgv.y)));
            }
        }
        float* dst = (s == 0) ? g_q : (s == 1) ? g_k : (s == 2) ? g_v : g_gate;
        #pragma unroll
        for (int t = 0; t < 4; t++) {
            int col = colbase + t * 8 + cq * 2;
            int h = col >> 5, d = col & 31;
            *(float2*)&dst[(((size_t)i0 * NH + h) * NRES + j0) * DH + d] =
                make_float2(acc[t][0], acc[t][1]);
            *(float2*)&dst[(((size_t)i1 * NH + h) * NRES + j1) * DH + d] =
                make_float2(acc[t][2], acc[t][3]);
        }
        __syncthreads();
    }
}

// =====================================================================
// Kernel B: attention per (i,h), fp16 m16n8k16, 256 thr, 2 blk/SM.
// (unchanged from R15 — protect)
// =====================================================================
#define KS_OFF    0
#define VS_OFF    (KS_OFF + 6400)
#define PS_OFF    (VS_OFF + 5248)
#define MSK_OFF   (PS_OFF + 10752)
#define SMEM_B    ((MSK_OFF + 320) * 4)

__global__ __launch_bounds__(256, 2) void kB(const float* __restrict__ mask)
{
    extern __shared__ float sm[];
    uint32_t* ksu = (uint32_t*)(sm + KS_OFF);
    uint32_t* vsu = (uint32_t*)(sm + VS_OFF);
    uint32_t* psu = (uint32_t*)(sm + PS_OFF);
    float* msk   = sm + MSK_OFF;

    int i = blockIdx.x, h = blockIdx.y;
    int tid = threadIdx.x, lane = tid & 31, w = tid >> 5;
    int g = lane >> 2, c = lane & 3;

    size_t base = ((size_t)i * NH + h) * (NRES * DH);
    const float* kg = g_k    + base;
    const float* qg = g_q    + base;
    const float* vg = g_v    + base;
    const float* gg = g_gate + base;

    for (int idx = tid; idx < 5120; idx += 256) {
        int kk = idx >> 4, d2 = idx & 15;
        float2 t = *(const float2*)&kg[kk * 32 + d2 * 2];
        ksu[kk * 20 + d2] = f2h2(t.x, t.y);
    }
    for (int idx = tid; idx < 5120; idx += 256) {
        int kkp = idx >> 5, d = idx & 31;
        float v0 = vg[(2 * kkp) * 32 + d];
        float v1 = vg[(2 * kkp + 1) * 32 + d];
        vsu[d * 164 + kkp] = f2h2(v0, v1);
    }
    for (int idx = tid; idx < NRES; idx += 256)
        msk[idx] = 1.0e9f * (mask[(size_t)i * NRES + idx] - 1.f);

    const float* bias_h = g_bias + (size_t)h * NN;
    uint32_t* pw = psu + w * 1344;

    __syncthreads();

    #pragma unroll 1
    for (int p = 0; p < 3; p++) {
        int tile = p * 8 + w;
        if (tile >= 20) break;
        int row0 = tile * 16 + g, row1 = row0 + 8;

        uint32_t qa[2][4];
        #pragma unroll
        for (int ds = 0; ds < 2; ds++) {
            float2 t0 = __ldg((const float2*)&qg[row0 * DH + 16 * ds + 2 * c]);
            float2 t1 = __ldg((const float2*)&qg[row1 * DH + 16 * ds + 2 * c]);
            float2 t2 = __ldg((const float2*)&qg[row0 * DH + 16 * ds + 2 * c + 8]);
            float2 t3 = __ldg((const float2*)&qg[row1 * DH + 16 * ds + 2 * c + 8]);
            qa[ds][0] = f2h2(t0.x, t0.y);
            qa[ds][1] = f2h2(t1.x, t1.y);
            qa[ds][2] = f2h2(t2.x, t2.y);
            qa[ds][3] = f2h2(t3.x, t3.y);
        }

        float o[4][4];
        #pragma unroll
        for (int t = 0; t < 4; t++)
            #pragma unroll
            for (int e = 0; e < 4; e++) o[t][e] = 0.f;
        float mA = -1e30f, mB = -1e30f, lA = 0.f, lB = 0.f;

        #pragma unroll 1
        for (int half = 0; half < 2; half++) {
            int khalf = half * 160;

            float s[20][4];
            #pragma unroll
            for (int t = 0; t < 20; t++)
                #pragma unroll
                for (int e = 0; e < 4; e++) s[t][e] = 0.f;

            #pragma unroll
            for (int ds = 0; ds < 2; ds++) {
                #pragma unroll
                for (int t = 0; t < 20; t++) {
                    int kr = (khalf + t * 8 + g) * 20 + 8 * ds + c;
                    uint32_t b0 = ksu[kr];
                    uint32_t b1 = ksu[kr + 4];
                    mma_f16(s[t], qa[ds][0], qa[ds][1], qa[ds][2], qa[ds][3], b0, b1);
                }
            }

            #pragma unroll
            for (int t = 0; t < 20; t++) {
                int col = khalf + t * 8 + c * 2;
                float2 mk = *(const float2*)&msk[col];
                float2 bA = __ldg((const float2*)&bias_h[(size_t)row0 * NRES + col]);
                float2 bB = __ldg((const float2*)&bias_h[(size_t)row1 * NRES + col]);
                s[t][0] += bA.x + mk.x;  s[t][1] += bA.y + mk.y;
                s[t][2] += bB.x + mk.x;  s[t][3] += bB.y + mk.y;
            }

            float hA = -1e30f, hB = -1e30f;
            #pragma unroll
            for (int t = 0; t < 20; t++) {
                hA = fmaxf(hA, fmaxf(s[t][0], s[t][1]));
                hB = fmaxf(hB, fmaxf(s[t][2], s[t][3]));
            }
            hA = fmaxf(hA, __shfl_xor_sync(0xffffffffu, hA, 1));
            hB = fmaxf(hB, __shfl_xor_sync(0xffffffffu, hB, 1));
            hA = fmaxf(hA, __shfl_xor_sync(0xffffffffu, hA, 2));
            hB = fmaxf(hB, __shfl_xor_sync(0xffffffffu, hB, 2));

            float nmA = fmaxf(mA, hA), nmB = fmaxf(mB, hB);
            float aA = __expf(mA - nmA), aB = __expf(mB - nmB);

            float sumA = 0.f, sumB = 0.f;
            #pragma unroll
            for (int t = 0; t < 20; t++) {
                s[t][0] = __expf(s[t][0] - nmA); sumA += s[t][0];
                s[t][1] = __expf(s[t][1] - nmA); sumA += s[t][1];
                s[t][2] = __expf(s[t][2] - nmB); sumB += s[t][2];
                s[t][3] = __expf(s[t][3] - nmB); sumB += s[t][3];
            }
            sumA += __shfl_xor_sync(0xffffffffu, sumA, 1);
            sumB += __shfl_xor_sync(0xffffffffu, sumB, 1);
            sumA += __shfl_xor_sync(0xffffffffu, sumA, 2);
            sumB += __shfl_xor_sync(0xffffffffu, sumB, 2);

            lA = lA * aA + sumA;  mA = nmA;
            lB = lB * aB + sumB;  mB = nmB;

            #pragma unroll
            for (int t = 0; t < 4; t++) {
                o[t][0] *= aA; o[t][1] *= aA;
                o[t][2] *= aB; o[t][3] *= aB;
            }

            #pragma unroll
            for (int t = 0; t < 20; t++) {
                pw[g * 84 + 4 * t + c]       = f2h2(s[t][0], s[t][1]);
                pw[(g + 8) * 84 + 4 * t + c] = f2h2(s[t][2], s[t][3]);
            }
            __syncwarp();

            #pragma unroll 2
            for (int ks = 0; ks < 10; ks++) {
                uint32_t a0 = pw[g * 84 + 8 * ks + c];
                uint32_t a1 = pw[(g + 8) * 84 + 8 * ks + c];
                uint32_t a2 = pw[g * 84 + 8 * ks + c + 4];
                uint32_t a3 = pw[(g + 8) * 84 + 8 * ks + c + 4];
                int kbase = (khalf >> 1) + 8 * ks + c;
                #pragma unroll
                for (int t = 0; t < 4; t++) {
                    int vr = (t * 8 + g) * 164 + kbase;
                    uint32_t b0 = vsu[vr];
                    uint32_t b1 = vsu[vr + 4];
                    mma_f16(o[t], a0, a1, a2, a3, b0, b1);
                }
            }
            __syncwarp();
        }

        float invA = 1.f / lA, invB = 1.f / lB;
        #pragma unroll
        for (int t = 0; t < 4; t++) {
            int col = t * 8 + c * 2;
            float2 gA = __ldg((const float2*)&gg[row0 * 32 + col]);
            float2 gB = __ldg((const float2*)&gg[row1 * 32 + col]);
            float2 rA = make_float2(o[t][0] * invA * gA.x, o[t][1] * invA * gA.y);
            float2 rB = make_float2(o[t][2] * invB * gB.x, o[t][3] * invB * gB.y);
            *(float2*)&g_og[((size_t)i * NRES + row0) * CDIM + h * DH + col] = rA;
            *(float2*)&g_og[((size_t)i * NRES + row1) * CDIM + h * DH + col] = rB;
        }
    }
}

// =====================================================================
// Kernel C (fp16 tensor, 1024 thr, 2 blocks/SM): out = og @ wo + bo.
// =====================================================================
#define KC_A  0
#define KC_WT (KC_A + 128*APH)
#define SMEM_C ((KC_WT + 128*APH) * 4)

__global__ __launch_bounds__(1024, 2) void kC(
    const float* __restrict__ bo, float* __restrict__ out)
{
    extern __shared__ float sm[];
    uint32_t* ao = (uint32_t*)(sm + KC_A);
    uint32_t* wt = (uint32_t*)(sm + KC_WT);

    int tid = threadIdx.x, lane = tid & 31, w = tid >> 5;
    int g2 = lane >> 2, cq = lane & 3;
    int rw = w & 7, nc = w >> 3;
    int colbase = nc * 32;
    int Rb = blockIdx.x * 128;

    // stage W (pre-converted fp16) and A (og -> fp16)
    const uint4* wsrc = (const uint4*)(g_wh + 4 * 8192);
    #pragma unroll
    for (int i = 0; i < 2; i++) {
        int idx4 = tid + i * 1024;
        int n = idx4 >> 4, k4 = idx4 & 15;
        uint4 vv = __ldg(&wsrc[idx4]);
        *(uint4*)&wt[n * APH + k4 * 4] = vv;
    }
    const float4* asrc = (const float4*)(g_og + (size_t)Rb * CDIM);
    #pragma unroll
    for (int i = 0; i < 4; i++) {
        int idx4 = tid + i * 1024;               // 4096 float4 = 128x128
        int r = idx4 >> 5, k8 = idx4 & 31;       // k8: 4-float group
        float4 av = asrc[idx4];
        uint2 packed = make_uint2(f2h2(av.x, av.y), f2h2(av.z, av.w));
        *(uint2*)&ao[r * APH + k8 * 2] = packed;
    }
    __syncthreads();

    int r0 = (rw << 4) + g2;

    float acc[4][4];
    #pragma unroll
    for (int t = 0; t < 4; t++)
        #pragma unroll
        for (int e = 0; e < 4; e++) acc[t][e] = 0.f;

    #pragma unroll 2
    for (int ks = 0; ks < 8; ks++) {
        int kc2 = ks * 8;
        uint32_t a0 = ao[r0 * APH + kc2 + cq];
        uint32_t a1 = ao[(r0 + 8) * APH + kc2 + cq];
        uint32_t a2 = ao[r0 * APH + kc2 + cq + 4];
        uint32_t a3 = ao[(r0 + 8) * APH + kc2 + cq + 4];
        #pragma unroll
        for (int t = 0; t < 4; t++) {
            int n0 = (colbase + t * 8 + g2) * APH + kc2;
            uint32_t b0 = wt[n0 + cq];
            uint32_t b1 = wt[n0 + cq + 4];
            mma_f16(acc[t], a0, a1, a2, a3, b0, b1);
        }
    }

    #pragma unroll
    for (int t = 0; t < 4; t++) {
        int col = colbase + t * 8 + cq * 2;
        float2 bb = __ldg((const float2*)&bo[col]);
        *(float2*)&out[(size_t)(Rb + r0) * CDIM + col] =
            make_float2(acc[t][0] + bb.x, acc[t][1] + bb.y);
        *(float2*)&out[(size_t)(Rb + r0 + 8) * CDIM + col] =
            make_float2(acc[t][2] + bb.x, acc[t][3] + bb.y);
    }
}

// =====================================================================
extern "C" void kernel_launch(void* const* d_in, const int* in_sizes, int n_in,
                              void* d_out, int out_size)
{
    const float* x    = (const float*)d_in[0];
    const float* mask = (const float*)d_in[1];
    const float* lng  = (const float*)d_in[2];
    const float* lnb  = (const float*)d_in[3];
    const float* wb   = (const float*)d_in[4];
    const float* wq   = (const float*)d_in[5];
    const float* wk   = (const float*)d_in[6];
    const float* wv   = (const float*)d_in[7];
    const float* wg   = (const float*)d_in[8];
    const float* bg   = (const float*)d_in[9];
    const float* wo   = (const float*)d_in[10];
    const float* bo   = (const float*)d_in[11];
    float* out = (float*)d_out;

    cudaFuncSetAttribute(kA, cudaFuncAttributeMaxDynamicSharedMemorySize, SMEM_A);
    cudaFuncSetAttribute(kB, cudaFuncAttributeMaxDynamicSharedMemorySize, SMEM_B);
    cudaFuncSetAttribute(kC, cudaFuncAttributeMaxDynamicSharedMemorySize, SMEM_C);

    kW<<<160, 256>>>(wq, wk, wv, wg, wo);
    kA<<<NN / 128, 1024, SMEM_A>>>(x, lng, lnb, wb, bg);
    kB<<<dim3(NRES, NH), 256, SMEM_B>>>(mask);
    kC<<<NN / 128, 1024, SMEM_C>>>(bo, out);
}

// round 17
// speedup vs baseline: 2.5515x; 1.0664x over previous
#include <cuda_runtime.h>
#include <cstdint>

#define NRES 320
#define CDIM 128
#define NH 4
#define DH 32
#define NN (NRES*NRES)
#define APH 68   // padded row stride (half2 words) for fp16 MMA tiles

// ---------- fp16 mma helpers ----------
__device__ __forceinline__ uint32_t f2h2(float lo, float hi) {
    uint32_t r; asm("cvt.rn.f16x2.f32 %0, %1, %2;" : "=r"(r) : "f"(hi), "f"(lo));
    return r;
}
__device__ __forceinline__ float h2lo_f(float v) {   // fp16 rounding of v
    uint32_t u; asm("cvt.rn.f16x2.f32 %0, %1, %1;" : "=r"(u) : "f"(v));
    float r; asm("cvt.f32.f16 %0, %1;" : "=f"(r) : "h"((unsigned short)(u & 0xffff)));
    return r;
}
__device__ __forceinline__ void mma_f16(float* d,
    uint32_t a0, uint32_t a1, uint32_t a2, uint32_t a3,
    uint32_t b0, uint32_t b1)
{
    asm volatile(
        "mma.sync.aligned.m16n8k16.row.col.f32.f16.f16.f32 "
        "{%0,%1,%2,%3}, {%4,%5,%6,%7}, {%8,%9}, {%0,%1,%2,%3};"
        : "+f"(d[0]), "+f"(d[1]), "+f"(d[2]), "+f"(d[3])
        : "r"(a0), "r"(a1), "r"(a2), "r"(a3), "r"(b0), "r"(b1));
}

// -------- device scratch --------
__device__ uint32_t g_qh  [(size_t)NRES*NH*NRES*16];   // fp16 q [i][h][j][d2]
__device__ uint32_t g_kh  [(size_t)NRES*NH*NRES*16];   // fp16 k
__device__ float g_v   [(size_t)NRES*NH*NRES*DH];
__device__ float g_gate[(size_t)NRES*NH*NRES*DH];
__device__ float g_og  [(size_t)NN*CDIM];
__device__ float g_bias[(size_t)NH*NN];                // [h][q][j]
__device__ uint32_t g_wh[5*128*64];                    // transposed fp16 weights

// =====================================================================
// Kernel W: one-shot transpose+convert of the 5 weight matrices (fp16).
// =====================================================================
__global__ __launch_bounds__(256, 4) void kW(
    const float* __restrict__ wq, const float* __restrict__ wk,
    const float* __restrict__ wv, const float* __restrict__ wg,
    const float* __restrict__ wo)
{
    int idx = blockIdx.x * 256 + threadIdx.x;    // 5*8192 words
    int s = idx >> 13, r = idx & 8191;
    int n = r >> 6, k2 = r & 63;
    const float* W = (s == 0) ? wq : (s == 1) ? wk : (s == 2) ? wv
                   : (s == 3) ? wg : wo;
    float w0 = W[(2 * k2) * 128 + n];
    float w1 = W[(2 * k2 + 1) * 128 + n];
    g_wh[idx] = f2h2(w0, w1);
}

// =====================================================================
// Kernel A (fp16 tensor, 1024 thr, 2 blocks/SM): LN + projections + bias.
// q/k stored fp16 (same rounding kB would apply); v/gate fp32.
// =====================================================================
#define KA_AHI 0
#define KA_ALO (KA_AHI + 128*APH)
#define KA_WT  (KA_ALO + 128*APH)
#define KA_SG  (KA_WT  + 128*APH)
#define KA_SB  (KA_SG + 128)
#define KA_WB  (KA_SB + 128)
#define SMEM_A ((KA_WB + 512) * 4)

__global__ __launch_bounds__(1024, 2) void kA(
    const float* __restrict__ x,   const float* __restrict__ lng,
    const float* __restrict__ lnb, const float* __restrict__ wb,
    const float* __restrict__ bg)
{
    extern __shared__ float sm[];
    uint32_t* ahi = (uint32_t*)(sm + KA_AHI);
    uint32_t* alo = (uint32_t*)(sm + KA_ALO);
    uint32_t* wt  = (uint32_t*)(sm + KA_WT);
    float* sg  = sm + KA_SG;
    float* sb  = sm + KA_SB;
    float* wbs = sm + KA_WB;

    int tid = threadIdx.x, lane = tid & 31, w = tid >> 5;
    int g2 = lane >> 2, cq = lane & 3;
    int rw = w & 7, nc = w >> 3;
    int colbase = nc * 32;
    int Rb = blockIdx.x * 128;

    if (tid < 128) { sg[tid] = lng[tid]; sb[tid] = lnb[tid]; }
    if (tid >= 128 && tid < 640) wbs[tid - 128] = wb[tid - 128];

    // ---- layernorm: 8 threads per row (16 elems each) ----
    int row = tid >> 3, sub = tid & 7;
    float xv[16];
    const float* xr = x + (size_t)(Rb + row) * CDIM + sub * 16;
    #pragma unroll
    for (int m4 = 0; m4 < 4; m4++) {
        float4 t = *(const float4*)(xr + m4 * 4);
        xv[m4*4+0] = t.x; xv[m4*4+1] = t.y; xv[m4*4+2] = t.z; xv[m4*4+3] = t.w;
    }
    float sum = 0.f, sq = 0.f;
    #pragma unroll
    for (int m = 0; m < 16; m++) { sum += xv[m]; sq += xv[m]*xv[m]; }
    #pragma unroll
    for (int off = 4; off >= 1; off >>= 1) {
        sum += __shfl_xor_sync(0xffffffffu, sum, off, 8);
        sq  += __shfl_xor_sync(0xffffffffu, sq,  off, 8);
    }
    float mu = sum * (1.f / CDIM);
    float rs = rsqrtf(sq * (1.f / CDIM) - mu * mu + 1e-5f);

    __syncthreads();   // sg/sb/wbs ready

    #pragma unroll
    for (int m2 = 0; m2 < 8; m2++) {
        int c0 = sub * 16 + 2 * m2;
        float v0 = (xv[2*m2]   - mu) * rs * sg[c0]     + sb[c0];
        float v1 = (xv[2*m2+1] - mu) * rs * sg[c0 + 1] + sb[c0 + 1];
        xv[2*m2] = v0; xv[2*m2+1] = v1;
        ahi[row * APH + sub * 8 + m2] = f2h2(v0, v1);
        alo[row * APH + sub * 8 + m2] = f2h2(v0 - h2lo_f(v0), v1 - h2lo_f(v1));
    }

    // ---- triangle bias in registers: partial dot + width-8 reduce ----
    {
        float part[4] = {0.f, 0.f, 0.f, 0.f};
        #pragma unroll
        for (int m = 0; m < 16; m++) {
            int cc = sub * 16 + m;
            float v = xv[m];
            #pragma unroll
            for (int j = 0; j < 4; j++) part[j] += v * wbs[cc * 4 + j];
        }
        #pragma unroll
        for (int off = 4; off >= 1; off >>= 1)
            #pragma unroll
            for (int j = 0; j < 4; j++)
                part[j] += __shfl_xor_sync(0xffffffffu, part[j], off, 8);
        if (sub == 0) {
            #pragma unroll
            for (int j = 0; j < 4; j++)
                g_bias[(size_t)j * NN + Rb + row] = part[j];
        }
    }
    __syncthreads();   // A tiles ready

    // ---- 4 projection chunks (fp16 MMA, K=16/step) ----
    int r0 = (rw << 4) + g2;
    int R0 = Rb + r0, R1 = R0 + 8;
    int i0 = R0 / NRES, j0 = R0 - i0 * NRES;
    int i1 = R1 / NRES, j1 = R1 - i1 * NRES;

    #pragma unroll 1
    for (int s = 0; s < 4; s++) {
        const uint4* src = (const uint4*)(g_wh + s * 8192);
        #pragma unroll
        for (int i = 0; i < 2; i++) {
            int idx4 = tid + i * 1024;
            int n = idx4 >> 4, k4 = idx4 & 15;
            uint4 vv = __ldg(&src[idx4]);
            *(uint4*)&wt[n * APH + k4 * 4] = vv;
        }
        __syncthreads();

        float acc[4][4];
        #pragma unroll
        for (int t = 0; t < 4; t++)
            #pragma unroll
            for (int e = 0; e < 4; e++) acc[t][e] = 0.f;

        #pragma unroll 2
        for (int ks = 0; ks < 8; ks++) {
            int kc2 = ks * 8;
            uint32_t h0 = ahi[r0 * APH + kc2 + cq];
            uint32_t h1 = ahi[(r0 + 8) * APH + kc2 + cq];
            uint32_t h2_ = ahi[r0 * APH + kc2 + cq + 4];
            uint32_t h3 = ahi[(r0 + 8) * APH + kc2 + cq + 4];
            if (s != 3) {
                uint32_t l0 = alo[r0 * APH + kc2 + cq];
                uint32_t l1 = alo[(r0 + 8) * APH + kc2 + cq];
                uint32_t l2 = alo[r0 * APH + kc2 + cq + 4];
                uint32_t l3 = alo[(r0 + 8) * APH + kc2 + cq + 4];
                #pragma unroll
                for (int t = 0; t < 4; t++) {
                    int n0 = (colbase + t * 8 + g2) * APH + kc2;
                    uint32_t b0 = wt[n0 + cq];
                    uint32_t b1 = wt[n0 + cq + 4];
                    mma_f16(acc[t], h0, h1, h2_, h3, b0, b1);
                    mma_f16(acc[t], l0, l1, l2, l3, b0, b1);
                }
            } else {
                #pragma unroll
                for (int t = 0; t < 4; t++) {
                    int n0 = (colbase + t * 8 + g2) * APH + kc2;
                    uint32_t b0 = wt[n0 + cq];
                    uint32_t b1 = wt[n0 + cq + 4];
                    mma_f16(acc[t], h0, h1, h2_, h3, b0, b1);
                }
            }
        }

        if (s == 0) {
            #pragma unroll
            for (int t = 0; t < 4; t++)
                #pragma unroll
                for (int e = 0; e < 4; e++) acc[t][e] *= 0.17677669529663687f;
        }
        if (s == 3) {
            #pragma unroll
            for (int t = 0; t < 4; t++) {
                int col = colbase + t * 8 + cq * 2;
                float2 bgv = __ldg((const float2*)&bg[col]);
                acc[t][0] = 1.f / (1.f + __expf(-(acc[t][0] + bgv.x)));
                acc[t][1] = 1.f / (1.f + __expf(-(acc[t][1] + bgv.y)));
                acc[t][2] = 1.f / (1.f + __expf(-(acc[t][2] + bgv.x)));
                acc[t][3] = 1.f / (1.f + __expf(-(acc[t][3] + bgv.y)));
            }
        }

        if (s < 2) {
            // q/k: fp16 store (one word per row-fragment) — same rounding
            // kB would apply on load.
            uint32_t* dst = (s == 0) ? g_qh : g_kh;
            #pragma unroll
            for (int t = 0; t < 4; t++) {
                int col = colbase + t * 8 + cq * 2;
                int h = col >> 5, d2 = (col & 31) >> 1;
                dst[(((size_t)i0 * NH + h) * NRES + j0) * 16 + d2] =
                    f2h2(acc[t][0], acc[t][1]);
                dst[(((size_t)i1 * NH + h) * NRES + j1) * 16 + d2] =
                    f2h2(acc[t][2], acc[t][3]);
            }
        } else {
            float* dst = (s == 2) ? g_v : g_gate;
            #pragma unroll
            for (int t = 0; t < 4; t++) {
                int col = colbase + t * 8 + cq * 2;
                int h = col >> 5, d = col & 31;
                *(float2*)&dst[(((size_t)i0 * NH + h) * NRES + j0) * DH + d] =
                    make_float2(acc[t][0], acc[t][1]);
                *(float2*)&dst[(((size_t)i1 * NH + h) * NRES + j1) * DH + d] =
                    make_float2(acc[t][2], acc[t][3]);
            }
        }
        __syncthreads();
    }
}

// =====================================================================
// Kernel B: attention per (i,h), fp16 m16n8k16, 256 thr, 2 blk/SM.
// K staged by uint4 copy from fp16 g_kh; q fragments direct LDG.32.
// =====================================================================
#define KS_OFF    0
#define VS_OFF    (KS_OFF + 6400)
#define PS_OFF    (VS_OFF + 5248)
#define MSK_OFF   (PS_OFF + 10752)
#define SMEM_B    ((MSK_OFF + 320) * 4)

__global__ __launch_bounds__(256, 2) void kB(const float* __restrict__ mask)
{
    extern __shared__ float sm[];
    uint32_t* ksu = (uint32_t*)(sm + KS_OFF);
    uint32_t* vsu = (uint32_t*)(sm + VS_OFF);
    uint32_t* psu = (uint32_t*)(sm + PS_OFF);
    float* msk   = sm + MSK_OFF;

    int i = blockIdx.x, h = blockIdx.y;
    int tid = threadIdx.x, lane = tid & 31, w = tid >> 5;
    int g = lane >> 2, c = lane & 3;

    size_t baseh = ((size_t)i * NH + h) * (NRES * 16);
    size_t base  = ((size_t)i * NH + h) * (NRES * DH);
    const uint32_t* kg = g_kh + baseh;
    const uint32_t* qg = g_qh + baseh;
    const float* vg = g_v    + base;
    const float* gg = g_gate + base;

    // stage K: pure uint4 copy (fp16 source)
    for (int idx = tid; idx < 1280; idx += 256) {
        int kk = idx >> 2, w4 = idx & 3;
        uint4 t = __ldg((const uint4*)(kg + kk * 16 + w4 * 4));
        *(uint4*)&ksu[kk * 20 + w4 * 4] = t;
    }
    // stage V transposed as fp16 [d][164 words] (kk pairs)
    for (int idx = tid; idx < 5120; idx += 256) {
        int kkp = idx >> 5, d = idx & 31;
        float v0 = vg[(2 * kkp) * 32 + d];
        float v1 = vg[(2 * kkp + 1) * 32 + d];
        vsu[d * 164 + kkp] = f2h2(v0, v1);
    }
    for (int idx = tid; idx < NRES; idx += 256)
        msk[idx] = 1.0e9f * (mask[(size_t)i * NRES + idx] - 1.f);

    const float* bias_h = g_bias + (size_t)h * NN;
    uint32_t* pw = psu + w * 1344;

    __syncthreads();

    #pragma unroll 1
    for (int p = 0; p < 3; p++) {
        int tile = p * 8 + w;
        if (tile >= 20) break;
        int row0 = tile * 16 + g, row1 = row0 + 8;

        // q fragments: direct LDG.32 from fp16 q
        uint32_t qa[2][4];
        #pragma unroll
        for (int ds = 0; ds < 2; ds++) {
            qa[ds][0] = __ldg(qg + row0 * 16 + 8 * ds + c);
            qa[ds][1] = __ldg(qg + row1 * 16 + 8 * ds + c);
            qa[ds][2] = __ldg(qg + row0 * 16 + 8 * ds + c + 4);
            qa[ds][3] = __ldg(qg + row1 * 16 + 8 * ds + c + 4);
        }

        float o[4][4];
        #pragma unroll
        for (int t = 0; t < 4; t++)
            #pragma unroll
            for (int e = 0; e < 4; e++) o[t][e] = 0.f;
        float mA = -1e30f, mB = -1e30f, lA = 0.f, lB = 0.f;

        #pragma unroll 1
        for (int half = 0; half < 2; half++) {
            int khalf = half * 160;

            float s[20][4];
            #pragma unroll
            for (int t = 0; t < 20; t++)
                #pragma unroll
                for (int e = 0; e < 4; e++) s[t][e] = 0.f;

            #pragma unroll
            for (int ds = 0; ds < 2; ds++) {
                #pragma unroll
                for (int t = 0; t < 20; t++) {
                    int kr = (khalf + t * 8 + g) * 20 + 8 * ds + c;
                    uint32_t b0 = ksu[kr];
                    uint32_t b1 = ksu[kr + 4];
                    mma_f16(s[t], qa[ds][0], qa[ds][1], qa[ds][2], qa[ds][3], b0, b1);
                }
            }

            #pragma unroll
            for (int t = 0; t < 20; t++) {
                int col = khalf + t * 8 + c * 2;
                float2 mk = *(const float2*)&msk[col];
                float2 bA = __ldg((const float2*)&bias_h[(size_t)row0 * NRES + col]);
                float2 bB = __ldg((const float2*)&bias_h[(size_t)row1 * NRES + col]);
                s[t][0] += bA.x + mk.x;  s[t][1] += bA.y + mk.y;
                s[t][2] += bB.x + mk.x;  s[t][3] += bB.y + mk.y;
            }

            float hA = -1e30f, hB = -1e30f;
            #pragma unroll
            for (int t = 0; t < 20; t++) {
                hA = fmaxf(hA, fmaxf(s[t][0], s[t][1]));
                hB = fmaxf(hB, fmaxf(s[t][2], s[t][3]));
            }
            hA = fmaxf(hA, __shfl_xor_sync(0xffffffffu, hA, 1));
            hB = fmaxf(hB, __shfl_xor_sync(0xffffffffu, hB, 1));
            hA = fmaxf(hA, __shfl_xor_sync(0xffffffffu, hA, 2));
            hB = fmaxf(hB, __shfl_xor_sync(0xffffffffu, hB, 2));

            float nmA = fmaxf(mA, hA), nmB = fmaxf(mB, hB);
            float aA = __expf(mA - nmA), aB = __expf(mB - nmB);

            float sumA = 0.f, sumB = 0.f;
            #pragma unroll
            for (int t = 0; t < 20; t++) {
                s[t][0] = __expf(s[t][0] - nmA); sumA += s[t][0];
                s[t][1] = __expf(s[t][1] - nmA); sumA += s[t][1];
                s[t][2] = __expf(s[t][2] - nmB); sumB += s[t][2];
                s[t][3] = __expf(s[t][3] - nmB); sumB += s[t][3];
            }
            sumA += __shfl_xor_sync(0xffffffffu, sumA, 1);
            sumB += __shfl_xor_sync(0xffffffffu, sumB, 1);
            sumA += __shfl_xor_sync(0xffffffffu, sumA, 2);
            sumB += __shfl_xor_sync(0xffffffffu, sumB, 2);

            lA = lA * aA + sumA;  mA = nmA;
            lB = lB * aB + sumB;  mB = nmB;

            #pragma unroll
            for (int t = 0; t < 4; t++) {
                o[t][0] *= aA; o[t][1] *= aA;
                o[t][2] *= aB; o[t][3] *= aB;
            }

            #pragma unroll
            for (int t = 0; t < 20; t++) {
                pw[g * 84 + 4 * t + c]       = f2h2(s[t][0], s[t][1]);
                pw[(g + 8) * 84 + 4 * t + c] = f2h2(s[t][2], s[t][3]);
            }
            __syncwarp();

            #pragma unroll 2
            for (int ks = 0; ks < 10; ks++) {
                uint32_t a0 = pw[g * 84 + 8 * ks + c];
                uint32_t a1 = pw[(g + 8) * 84 + 8 * ks + c];
                uint32_t a2 = pw[g * 84 + 8 * ks + c + 4];
                uint32_t a3 = pw[(g + 8) * 84 + 8 * ks + c + 4];
                int kbase = (khalf >> 1) + 8 * ks + c;
                #pragma unroll
                for (int t = 0; t < 4; t++) {
                    int vr = (t * 8 + g) * 164 + kbase;
                    uint32_t b0 = vsu[vr];
                    uint32_t b1 = vsu[vr + 4];
                    mma_f16(o[t], a0, a1, a2, a3, b0, b1);
                }
            }
            __syncwarp();
        }

        float invA = 1.f / lA, invB = 1.f / lB;
        #pragma unroll
        for (int t = 0; t < 4; t++) {
            int col = t * 8 + c * 2;
            float2 gA = __ldg((const float2*)&gg[row0 * 32 + col]);
            float2 gB = __ldg((const float2*)&gg[row1 * 32 + col]);
            float2 rA = make_float2(o[t][0] * invA * gA.x, o[t][1] * invA * gA.y);
            float2 rB = make_float2(o[t][2] * invB * gB.x, o[t][3] * invB * gB.y);
            *(float2*)&g_og[((size_t)i * NRES + row0) * CDIM + h * DH + col] = rA;
            *(float2*)&g_og[((size_t)i * NRES + row1) * CDIM + h * DH + col] = rB;
        }
    }
}

// =====================================================================
// Kernel C (fp16 tensor, 1024 thr, 2 blocks/SM): out = og @ wo + bo.
// (unchanged from R16)
// =====================================================================
#define KC_A  0
#define KC_WT (KC_A + 128*APH)
#define SMEM_C ((KC_WT + 128*APH) * 4)

__global__ __launch_bounds__(1024, 2) void kC(
    const float* __restrict__ bo, float* __restrict__ out)
{
    extern __shared__ float sm[];
    uint32_t* ao = (uint32_t*)(sm + KC_A);
    uint32_t* wt = (uint32_t*)(sm + KC_WT);

    int tid = threadIdx.x, lane = tid & 31, w = tid >> 5;
    int g2 = lane >> 2, cq = lane & 3;
    int rw = w & 7, nc = w >> 3;
    int colbase = nc * 32;
    int Rb = blockIdx.x * 128;

    const uint4* wsrc = (const uint4*)(g_wh + 4 * 8192);
    #pragma unroll
    for (int i = 0; i < 2; i++) {
        int idx4 = tid + i * 1024;
        int n = idx4 >> 4, k4 = idx4 & 15;
        uint4 vv = __ldg(&wsrc[idx4]);
        *(uint4*)&wt[n * APH + k4 * 4] = vv;
    }
    const float4* asrc = (const float4*)(g_og + (size_t)Rb * CDIM);
    #pragma unroll
    for (int i = 0; i < 4; i++) {
        int idx4 = tid + i * 1024;
        int r = idx4 >> 5, k8 = idx4 & 31;
        float4 av = asrc[idx4];
        uint2 packed = make_uint2(f2h2(av.x, av.y), f2h2(av.z, av.w));
        *(uint2*)&ao[r * APH + k8 * 2] = packed;
    }
    __syncthreads();

    int r0 = (rw << 4) + g2;

    float acc[4][4];
    #pragma unroll
    for (int t = 0; t < 4; t++)
        #pragma unroll
        for (int e = 0; e < 4; e++) acc[t][e] = 0.f;

    #pragma unroll 2
    for (int ks = 0; ks < 8; ks++) {
        int kc2 = ks * 8;
        uint32_t a0 = ao[r0 * APH + kc2 + cq];
        uint32_t a1 = ao[(r0 + 8) * APH + kc2 + cq];
        uint32_t a2 = ao[r0 * APH + kc2 + cq + 4];
        uint32_t a3 = ao[(r0 + 8) * APH + kc2 + cq + 4];
        #pragma unroll
        for (int t = 0; t < 4; t++) {
            int n0 = (colbase + t * 8 + g2) * APH + kc2;
            uint32_t b0 = wt[n0 + cq];
            uint32_t b1 = wt[n0 + cq + 4];
            mma_f16(acc[t], a0, a1, a2, a3, b0, b1);
        }
    }

    #pragma unroll
    for (int t = 0; t < 4; t++) {
        int col = colbase + t * 8 + cq * 2;
        float2 bb = __ldg((const float2*)&bo[col]);
        *(float2*)&out[(size_t)(Rb + r0) * CDIM + col] =
            make_float2(acc[t][0] + bb.x, acc[t][1] + bb.y);
        *(float2*)&out[(size_t)(Rb + r0 + 8) * CDIM + col] =
            make_float2(acc[t][2] + bb.x, acc[t][3] + bb.y);
    }
}

// =====================================================================
extern "C" void kernel_launch(void* const* d_in, const int* in_sizes, int n_in,
                              void* d_out, int out_size)
{
    const float* x    = (const float*)d_in[0];
    const float* mask = (const float*)d_in[1];
    const float* lng  = (const float*)d_in[2];
    const float* lnb  = (const float*)d_in[3];
    const float* wb   = (const float*)d_in[4];
    const float* wq   = (const float*)d_in[5];
    const float* wk   = (const float*)d_in[6];
    const float* wv   = (const float*)d_in[7];
    const float* wg   = (const float*)d_in[8];
    const float* bg   = (const float*)d_in[9];
    const float* wo   = (const float*)d_in[10];
    const float* bo   = (const float*)d_in[11];
    float* out = (float*)d_out;

    cudaFuncSetAttribute(kA, cudaFuncAttributeMaxDynamicSharedMemorySize, SMEM_A);
    cudaFuncSetAttribute(kB, cudaFuncAttributeMaxDynamicSharedMemorySize, SMEM_B);
    cudaFuncSetAttribute(kC, cudaFuncAttributeMaxDynamicSharedMemorySize, SMEM_C);

    kW<<<160, 256>>>(wq, wk, wv, wg, wo);
    kA<<<NN / 128, 1024, SMEM_A>>>(x, lng, lnb, wb, bg);
    kB<<<dim3(NRES, NH), 256, SMEM_B>>>(mask);
    kC<<<NN / 128, 1024, SMEM_C>>>(bo, out);
}